// round 2
// baseline (speedup 1.0000x reference)
#include <cuda_runtime.h>
#include <cstdint>
#include <math.h>

#define Bz 512
#define Lz 200
#define Ez 256
#define Hz 128
#define G4 512          // 4*H
#define Dz 256
#define Tz 6
#define NL (Bz*Lz)      // 102400

// -------- device scratch (static, allowed) --------
__device__ float g_X[NL*Ez];        // gathered embeddings, later reused as h2
__device__ float g_xgf[NL*G4];      // forward input gates
__device__ float g_xgb[NL*G4];      // backward input gates (natural position order)
__device__ float g_h[NL*Dz];        // BiLSTM hidden concat [hf|hb]
__device__ float g_m1[NL*Dz];       // MLP intermediate
__device__ float g_logits[NL*Tz];   // emissions
__device__ float g_Whh4_f[Hz*G4];   // Whh repacked [k/4][g][4]
__device__ float g_Whh4_b[Hz*G4];
__device__ unsigned char g_bp[Bz*Lz*Tz]; // viterbi backpointers

// ---------------- gather embeddings ----------------
__global__ void gather_kernel(const int* __restrict__ sent, const float* __restrict__ emb) {
    int idx = blockIdx.x * 256 + threadIdx.x;       // float4 units
    if (idx >= NL * (Ez / 4)) return;
    int n  = idx >> 6;           // Ez/4 = 64
    int e4 = idx & 63;
    int tok = sent[n];
    ((float4*)g_X)[idx] = ((const float4*)emb)[(size_t)tok * 64 + e4];
}

// ---------------- repack Whh ----------------
// Whh is [G4][Hz] row-major. Build Whh4[(k>>2)*G4*4 + g*4 + (k&3)] = Whh[g][k]
__global__ void prep_whh(const float* __restrict__ Whh_f, const float* __restrict__ Whh_b) {
    int idx = blockIdx.x * 256 + threadIdx.x;
    if (idx >= G4 * Hz) return;
    int g = idx / Hz, k = idx % Hz;
    int dst = (k >> 2) * (G4 * 4) + g * 4 + (k & 3);
    g_Whh4_f[dst] = Whh_f[idx];
    g_Whh4_b[dst] = Whh_b[idx];
}

// ---------------- generic fp32 GEMM: C[N,M] = A[N,K] @ W[M,K]^T + bias (+leaky) ----------------
// Requires N%128==0, M%128==0, K%16==0.
__global__ __launch_bounds__(256) void gemm_bias_act(
    const float* __restrict__ A, const float* __restrict__ W,
    const float* __restrict__ bias1, const float* __restrict__ bias2,
    float* __restrict__ C, int N, int M, int K, int act)
{
    __shared__ float As[16][128];
    __shared__ float Bs[16][128];
    int tid = threadIdx.x;
    int tx = tid & 15, ty = tid >> 4;
    int row0 = blockIdx.y * 128;
    int col0 = blockIdx.x * 128;
    int lrow = tid >> 1;            // 0..127
    int lk   = (tid & 1) * 8;       // 0 or 8

    float acc[8][8];
    #pragma unroll
    for (int i = 0; i < 8; i++)
        #pragma unroll
        for (int j = 0; j < 8; j++) acc[i][j] = 0.f;

    for (int k0 = 0; k0 < K; k0 += 16) {
        const float* ap = A + (size_t)(row0 + lrow) * K + k0 + lk;
        float4 a0 = *(const float4*)ap;
        float4 a1 = *(const float4*)(ap + 4);
        As[lk+0][lrow] = a0.x; As[lk+1][lrow] = a0.y; As[lk+2][lrow] = a0.z; As[lk+3][lrow] = a0.w;
        As[lk+4][lrow] = a1.x; As[lk+5][lrow] = a1.y; As[lk+6][lrow] = a1.z; As[lk+7][lrow] = a1.w;
        const float* wp = W + (size_t)(col0 + lrow) * K + k0 + lk;
        float4 b0 = *(const float4*)wp;
        float4 b1 = *(const float4*)(wp + 4);
        Bs[lk+0][lrow] = b0.x; Bs[lk+1][lrow] = b0.y; Bs[lk+2][lrow] = b0.z; Bs[lk+3][lrow] = b0.w;
        Bs[lk+4][lrow] = b1.x; Bs[lk+5][lrow] = b1.y; Bs[lk+6][lrow] = b1.z; Bs[lk+7][lrow] = b1.w;
        __syncthreads();
        #pragma unroll
        for (int k = 0; k < 16; k++) {
            float a[8], b[8];
            *(float4*)&a[0] = *(const float4*)&As[k][ty*8];
            *(float4*)&a[4] = *(const float4*)&As[k][ty*8+4];
            *(float4*)&b[0] = *(const float4*)&Bs[k][tx*8];
            *(float4*)&b[4] = *(const float4*)&Bs[k][tx*8+4];
            #pragma unroll
            for (int i = 0; i < 8; i++)
                #pragma unroll
                for (int j = 0; j < 8; j++)
                    acc[i][j] = fmaf(a[i], b[j], acc[i][j]);
        }
        __syncthreads();
    }

    float bc[8];
    #pragma unroll
    for (int j = 0; j < 8; j++) {
        int c = col0 + tx*8 + j;
        bc[j] = bias1[c] + (bias2 ? bias2[c] : 0.f);
    }
    #pragma unroll
    for (int i = 0; i < 8; i++) {
        float* crow = C + (size_t)(row0 + ty*8 + i) * M + col0 + tx*8;
        float v[8];
        #pragma unroll
        for (int j = 0; j < 8; j++) {
            float x = acc[i][j] + bc[j];
            v[j] = act ? (x >= 0.f ? x : 0.01f * x) : x;
        }
        *(float4*)(crow)     = *(float4*)&v[0];
        *(float4*)(crow + 4) = *(float4*)&v[4];
    }
}

// ---------------- BiLSTM recurrence (persistent over all 200 steps) ----------------
// grid = (Bz/8, 2 dirs), block = 512 threads (one per gate g)
__global__ __launch_bounds__(512) void lstm_kernel() {
    int dir = blockIdx.y;
    int b0  = blockIdx.x * 8;
    const float* xg = dir ? g_xgb : g_xgf;
    const float* W4 = dir ? g_Whh4_b : g_Whh4_f;

    __shared__ float hs[8][Hz];
    __shared__ float cs[8][Hz];
    __shared__ float gb[8][G4];

    int g = threadIdx.x;
    for (int idx = g; idx < 8 * Hz; idx += 512) {
        ((float*)hs)[idx] = 0.f;
        ((float*)cs)[idx] = 0.f;
    }
    __syncthreads();

    for (int t = 0; t < Lz; t++) {
        int pos = dir ? (Lz - 1 - t) : t;
        float acc[8];
        #pragma unroll
        for (int r = 0; r < 8; r++)
            acc[r] = xg[((size_t)(b0 + r) * Lz + pos) * G4 + g];

        #pragma unroll 8
        for (int kc = 0; kc < Hz / 4; kc++) {
            float4 w = *(const float4*)(W4 + kc * (G4 * 4) + (g << 2));
            #pragma unroll
            for (int r = 0; r < 8; r++) {
                float4 hv = *(const float4*)(&hs[r][kc << 2]);
                acc[r] = fmaf(w.x, hv.x, acc[r]);
                acc[r] = fmaf(w.y, hv.y, acc[r]);
                acc[r] = fmaf(w.z, hv.z, acc[r]);
                acc[r] = fmaf(w.w, hv.w, acc[r]);
            }
        }
        #pragma unroll
        for (int r = 0; r < 8; r++) gb[r][g] = acc[r];
        __syncthreads();

        #pragma unroll
        for (int rep = 0; rep < 2; rep++) {
            int idx = rep * 512 + g;
            int r = idx >> 7, j = idx & 127;
            float xi = gb[r][j];
            float xf = gb[r][j + Hz];
            float xc = gb[r][j + 2 * Hz];
            float xo = gb[r][j + 3 * Hz];
            float ii = 1.f / (1.f + expf(-xi));
            float ff = 1.f / (1.f + expf(-xf));
            float gg = tanhf(xc);
            float oo = 1.f / (1.f + expf(-xo));
            float c  = ff * cs[r][j] + ii * gg;
            float h  = oo * tanhf(c);
            cs[r][j] = c;
            hs[r][j] = h;
            g_h[((size_t)(b0 + r) * Lz + pos) * Dz + dir * Hz + j] = h;
        }
        __syncthreads();
    }
}

// ---------------- tag projection: logits[n][t] = leaky(h2[n]·Wt[t] + bt[t]) ----------------
__global__ __launch_bounds__(256) void logits_kernel(
    const float* __restrict__ H2, const float* __restrict__ Wt,
    const float* __restrict__ bt)
{
    __shared__ float wts[Tz * Dz];
    __shared__ float bts[Tz];
    for (int i = threadIdx.x; i < Tz * Dz; i += 256) wts[i] = Wt[i];
    if (threadIdx.x < Tz) bts[threadIdx.x] = bt[threadIdx.x];
    __syncthreads();

    int n    = (blockIdx.x * 256 + threadIdx.x) >> 5;
    int lane = threadIdx.x & 31;
    if (n >= NL) return;
    float acc[Tz];
    #pragma unroll
    for (int t = 0; t < Tz; t++) acc[t] = 0.f;
    const float* hrow = H2 + (size_t)n * Dz;
    for (int k = lane; k < Dz; k += 32) {
        float x = hrow[k];
        #pragma unroll
        for (int t = 0; t < Tz; t++) acc[t] = fmaf(x, wts[t * Dz + k], acc[t]);
    }
    #pragma unroll
    for (int t = 0; t < Tz; t++)
        #pragma unroll
        for (int off = 16; off; off >>= 1)
            acc[t] += __shfl_xor_sync(0xffffffffu, acc[t], off);
    if (lane == 0) {
        #pragma unroll
        for (int t = 0; t < Tz; t++) {
            float x = acc[t] + bts[t];
            g_logits[(size_t)n * Tz + t] = (x >= 0.f ? x : 0.01f * x);
        }
    }
}

// ---------------- per-sample Viterbi ----------------
__global__ void viterbi_kernel(const float* __restrict__ trans,
                               float* __restrict__ out, int score_off, int path_off)
{
    __shared__ float tr[Tz * Tz];
    if (threadIdx.x < Tz * Tz) tr[threadIdx.x] = trans[threadIdx.x];
    __syncthreads();
    int b = blockIdx.x * blockDim.x + threadIdx.x;
    if (b >= Bz) return;

    const float* lg = g_logits + (size_t)b * Lz * Tz;
    float prev[Tz];
    #pragma unroll
    for (int t = 0; t < Tz; t++) prev[t] = lg[t];

    for (int l = 1; l < Lz; l++) {
        float cur[Tz];
        #pragma unroll
        for (int j = 0; j < Tz; j++) {
            float best = prev[0] + tr[j];
            int bi = 0;
            #pragma unroll
            for (int i = 1; i < Tz; i++) {
                float v = prev[i] + tr[i * Tz + j];
                if (v > best) { best = v; bi = i; }
            }
            g_bp[((size_t)b * Lz + l) * Tz + j] = (unsigned char)bi;
            cur[j] = lg[(size_t)l * Tz + j] + best;
        }
        #pragma unroll
        for (int j = 0; j < Tz; j++) prev[j] = cur[j];
    }
    float best = prev[0];
    int last = 0;
    #pragma unroll
    for (int i = 1; i < Tz; i++) if (prev[i] > best) { best = prev[i]; last = i; }

    if (score_off >= 0) out[score_off + b] = best;
    if (path_off >= 0) {
        int tag = last;
        out[path_off + (size_t)b * Lz + (Lz - 1)] = (float)tag;
        for (int l = Lz - 1; l >= 1; l--) {
            tag = g_bp[((size_t)b * Lz + l) * Tz + tag];
            out[path_off + (size_t)b * Lz + (l - 1)] = (float)tag;
        }
    }
}

// ---------------- launch ----------------
extern "C" void kernel_launch(void* const* d_in, const int* in_sizes, int n_in,
                              void* d_out, int out_size) {
    const int*   sent  = (const int*)d_in[0];
    // d_in[1] real_length: always == L, unused
    const float* emb   = (const float*)d_in[2];
    const float* Wih_f = (const float*)d_in[3];
    const float* Whh_f = (const float*)d_in[4];
    const float* bih_f = (const float*)d_in[5];
    const float* bhh_f = (const float*)d_in[6];
    const float* Wih_b = (const float*)d_in[7];
    const float* Whh_b = (const float*)d_in[8];
    const float* bih_b = (const float*)d_in[9];
    const float* bhh_b = (const float*)d_in[10];
    const float* W1    = (const float*)d_in[11];
    const float* b1    = (const float*)d_in[12];
    const float* W2    = (const float*)d_in[13];
    const float* b2    = (const float*)d_in[14];
    const float* Wt    = (const float*)d_in[15];
    const float* bt    = (const float*)d_in[16];
    const float* trans = (const float*)d_in[17];
    float* out = (float*)d_out;

    float *X, *xgf, *xgb, *hbuf, *m1;
    cudaGetSymbolAddress((void**)&X,    g_X);
    cudaGetSymbolAddress((void**)&xgf,  g_xgf);
    cudaGetSymbolAddress((void**)&xgb,  g_xgb);
    cudaGetSymbolAddress((void**)&hbuf, g_h);
    cudaGetSymbolAddress((void**)&m1,   g_m1);

    // zero the output buffer (it is poisoned; covers any padding beyond what we write)
    cudaMemsetAsync(d_out, 0, (size_t)out_size * sizeof(float));

    // 1. gather embeddings
    gather_kernel<<<NL * (Ez / 4) / 256, 256>>>(sent, emb);
    // 2. repack Whh
    prep_whh<<<(G4 * Hz + 255) / 256, 256>>>(Whh_f, Whh_b);
    // 3. input-gate GEMMs (both directions)
    gemm_bias_act<<<dim3(G4 / 128, NL / 128), 256>>>(X, Wih_f, bih_f, bhh_f, xgf, NL, G4, Ez, 0);
    gemm_bias_act<<<dim3(G4 / 128, NL / 128), 256>>>(X, Wih_b, bih_b, bhh_b, xgb, NL, G4, Ez, 0);
    // 4. BiLSTM recurrence
    lstm_kernel<<<dim3(Bz / 8, 2), 512>>>();
    // 5. MLP
    gemm_bias_act<<<dim3(Dz / 128, NL / 128), 256>>>(hbuf, W1, b1, nullptr, m1, NL, Dz, Dz, 1);
    gemm_bias_act<<<dim3(Dz / 128, NL / 128), 256>>>(m1, W2, b2, nullptr, X, NL, Dz, Dz, 1);
    // 6. tag projection
    logits_kernel<<<NL / 8, 256>>>(X, Wt, bt);
    // 7. viterbi + output
    int score_off = -1, path_off = -1;
    if (out_size >= Bz * (Lz + 1))      { score_off = 0; path_off = Bz; }
    else if (out_size >= Bz * Lz)       { path_off = 0; }
    else                                { score_off = 0; }
    viterbi_kernel<<<(Bz + 255) / 256, 256>>>(trans, out, score_off, path_off);
}

// round 4
// speedup vs baseline: 1.3167x; 1.3167x over previous
#include <cuda_runtime.h>
#include <cuda_bf16.h>
#include <cstdint>
#include <math.h>

#define Bz 512
#define Lz 200
#define Ez 256
#define Hz 128
#define G4 512          // 4*H
#define Dz 256
#define Tz 6
#define NL (Bz*Lz)      // 102400

// ---------------- device scratch ----------------
__device__ float g_X[NL*Dz];          // h2 (MLP2 fp32 output)
__device__ float g_xgf[NL*G4];        // forward input gates (fp32)
__device__ float g_xgb[NL*G4];        // backward input gates (fp32)
__device__ float g_logits[NL*Tz];
__device__ float g_Whh4_f[Hz*G4];
__device__ float g_Whh4_b[Hz*G4];
__device__ unsigned char g_bp[Bz*Lz*Tz];

// bf16 split-2 operand buffers (value = hi + lo)
__device__ __nv_bfloat16 g_Xh[NL*Ez],  g_Xl[NL*Ez];     // embeddings
__device__ __nv_bfloat16 g_Hh[NL*Dz],  g_Hl[NL*Dz];     // BiLSTM hidden
__device__ __nv_bfloat16 g_M1h[NL*Dz], g_M1l[NL*Dz];    // MLP1 out
__device__ __nv_bfloat16 g_WFh[G4*Ez], g_WFl[G4*Ez];    // Wih_f
__device__ __nv_bfloat16 g_WBh[G4*Ez], g_WBl[G4*Ez];    // Wih_b
__device__ __nv_bfloat16 g_W1h[Dz*Dz], g_W1l[Dz*Dz];
__device__ __nv_bfloat16 g_W2h[Dz*Dz], g_W2l[Dz*Dz];

// ================= helpers =================
__device__ __forceinline__ uint32_t smem_u32(const void* p) {
    uint32_t a;
    asm("{ .reg .u64 t; cvta.to.shared.u64 t, %1; cvt.u32.u64 %0, t; }" : "=r"(a) : "l"(p));
    return a;
}
__device__ __forceinline__ uint32_t swz(uint32_t off) {        // SW128-style XOR swizzle
    return off ^ ((off >> 3) & 0x70);
}
__device__ __forceinline__ void ldm4(uint32_t* r, uint32_t addr) {
    asm volatile("ldmatrix.sync.aligned.m8n8.x4.shared.b16 {%0,%1,%2,%3}, [%4];"
        : "=r"(r[0]), "=r"(r[1]), "=r"(r[2]), "=r"(r[3]) : "r"(addr));
}
__device__ __forceinline__ void mma16816(float* d, const uint32_t* a, const uint32_t* b) {
    asm volatile("mma.sync.aligned.m16n8k16.row.col.f32.bf16.bf16.f32 "
        "{%0,%1,%2,%3}, {%4,%5,%6,%7}, {%8,%9}, {%0,%1,%2,%3};"
        : "+f"(d[0]), "+f"(d[1]), "+f"(d[2]), "+f"(d[3])
        : "r"(a[0]), "r"(a[1]), "r"(a[2]), "r"(a[3]), "r"(b[0]), "r"(b[1]));
}
__device__ __forceinline__ void split2(float x, __nv_bfloat16& h, __nv_bfloat16& l) {
    h = __float2bfloat16(x);
    l = __float2bfloat16(x - __bfloat162float(h));
}

// ---------------- gather embeddings -> bf16 split2 ----------------
__global__ void gather_conv(const int* __restrict__ sent, const float* __restrict__ emb) {
    int idx = blockIdx.x * 256 + threadIdx.x;     // float4 units over NL x 256
    if (idx >= NL * (Ez / 4)) return;
    int n = idx >> 6, e4 = idx & 63;
    int tok = sent[n];
    float4 v = ((const float4*)emb)[(size_t)tok * 64 + e4];
    size_t o = (size_t)idx * 4;
    float vv[4] = {v.x, v.y, v.z, v.w};
    __nv_bfloat16 hh[4], ll[4];
    #pragma unroll
    for (int k = 0; k < 4; k++) split2(vv[k], hh[k], ll[k]);
    __nv_bfloat162 p;
    p.x = hh[0]; p.y = hh[1]; ((__nv_bfloat162*)(g_Xh + o))[0] = p;
    p.x = hh[2]; p.y = hh[3]; ((__nv_bfloat162*)(g_Xh + o))[1] = p;
    p.x = ll[0]; p.y = ll[1]; ((__nv_bfloat162*)(g_Xl + o))[0] = p;
    p.x = ll[2]; p.y = ll[3]; ((__nv_bfloat162*)(g_Xl + o))[1] = p;
}

// ---------------- fp32 -> split2 ----------------
__global__ void conv2(const float* __restrict__ src, __nv_bfloat16* __restrict__ hi,
                      __nv_bfloat16* __restrict__ lo, int n) {
    int i = blockIdx.x * 256 + threadIdx.x;
    if (i >= n) return;
    __nv_bfloat16 h, l;
    split2(src[i], h, l);
    hi[i] = h; lo[i] = l;
}

// ---------------- repack Whh ----------------
__global__ void prep_whh(const float* __restrict__ Whh_f, const float* __restrict__ Whh_b) {
    int idx = blockIdx.x * 256 + threadIdx.x;
    if (idx >= G4 * Hz) return;
    int g = idx / Hz, k = idx % Hz;
    int dst = (k >> 2) * (G4 * 4) + g * 4 + (k & 3);
    g_Whh4_f[dst] = Whh_f[idx];
    g_Whh4_b[dst] = Whh_b[idx];
}

// ================= HMMA split-bf16 GEMM =================
// C[NL rows, Mout cols] = A[.,256] @ B[Mout,256]^T + bias ; A,B given as (hi,lo) bf16 pairs.
// mode 0: fp32 out, bias1+bias2, no act
// mode 1: fp32 out, bias1, leaky
// mode 2: bf16 split2 out, bias1, leaky
__global__ __launch_bounds__(256) void gemm_mma(
    const __nv_bfloat16* __restrict__ Ah, const __nv_bfloat16* __restrict__ Al,
    const __nv_bfloat16* __restrict__ Bh, const __nv_bfloat16* __restrict__ Bl,
    const float* __restrict__ bias1, const float* __restrict__ bias2,
    float* __restrict__ Cf,
    __nv_bfloat16* __restrict__ C2h, __nv_bfloat16* __restrict__ C2l,
    int Mout, int mode)
{
    __shared__ __align__(1024) char sm[32768];
    char* smA = sm;
    char* smB = sm + 16384;
    uint32_t sA = smem_u32(smA), sB = smem_u32(smB);

    int tid = threadIdx.x, wid = tid >> 5, lane = tid & 31;
    int row0 = blockIdx.y * 128;
    int col0 = blockIdx.x * 128;
    int wm0 = (wid & 1) * 64;        // warp M offset within tile
    int wn0 = (wid >> 1) * 32;       // warp N offset within tile

    float acc[4][4][4];
    #pragma unroll
    for (int i = 0; i < 4; i++)
        #pragma unroll
        for (int j = 0; j < 4; j++)
            #pragma unroll
            for (int k = 0; k < 4; k++) acc[i][j][k] = 0.f;

    // ldmatrix per-lane addressing pieces
    int arow = ((lane >> 3) & 1) * 8 + (lane & 7);       // + am*16
    int acb  = (lane >> 4) << 4;                         // + ks*32 (+64 for lo)
    int brow = ((lane >> 4) << 3) + (lane & 7);          // + np*16
    int bcb  = ((lane >> 3) & 1) << 4;                   // + ks*32 (+64 for lo)

    for (int kc = 0; kc < 8; kc++) {
        int k0 = kc * 32;
        __syncthreads();
        #pragma unroll
        for (int j = 0; j < 4; j++) {
            int idx = tid + j * 256;           // 0..1023
            int r = idx >> 3, s = idx & 7;     // s<4: hi seg, s>=4: lo seg
            const __nv_bfloat16* src = (s < 4 ? Ah : Al) + (size_t)(row0 + r) * 256 + k0 + (s & 3) * 8;
            *(uint4*)(smA + swz(r * 128 + s * 16)) = *(const uint4*)src;
        }
        #pragma unroll
        for (int j = 0; j < 4; j++) {
            int idx = tid + j * 256;
            int r = idx >> 3, s = idx & 7;
            const __nv_bfloat16* src = (s < 4 ? Bh : Bl) + (size_t)(col0 + r) * 256 + k0 + (s & 3) * 8;
            *(uint4*)(smB + swz(r * 128 + s * 16)) = *(const uint4*)src;
        }
        __syncthreads();

        #pragma unroll
        for (int ks = 0; ks < 2; ks++) {
            uint32_t aH[4][4], aL[4][4], bH[2][4], bL[2][4];
            #pragma unroll
            for (int am = 0; am < 4; am++) {
                int r = wm0 + am * 16 + arow;
                ldm4(aH[am], sA + swz((uint32_t)(r * 128 + ks * 32 + acb)));
                ldm4(aL[am], sA + swz((uint32_t)(r * 128 + 64 + ks * 32 + acb)));
            }
            #pragma unroll
            for (int np = 0; np < 2; np++) {
                int r = wn0 + np * 16 + brow;
                ldm4(bH[np], sB + swz((uint32_t)(r * 128 + ks * 32 + bcb)));
                ldm4(bL[np], sB + swz((uint32_t)(r * 128 + 64 + ks * 32 + bcb)));
            }
            #pragma unroll
            for (int am = 0; am < 4; am++) {
                #pragma unroll
                for (int bn = 0; bn < 4; bn++) {
                    const uint32_t* bh = &bH[bn >> 1][(bn & 1) * 2];
                    const uint32_t* bl = &bL[bn >> 1][(bn & 1) * 2];
                    mma16816(acc[am][bn], aH[am], bh);   // Ah*Bh
                    mma16816(acc[am][bn], aH[am], bl);   // Ah*Bl
                    mma16816(acc[am][bn], aL[am], bh);   // Al*Bh
                }
            }
        }
    }

    // ---------------- epilogue ----------------
    int rg = row0 + wm0 + (lane >> 2);          // + am*16 (+8)
    int cg = col0 + wn0 + (lane & 3) * 2;       // + bn*8
    #pragma unroll
    for (int bn = 0; bn < 4; bn++) {
        int col = cg + bn * 8;
        float bb0 = bias1[col]     + (bias2 ? bias2[col]     : 0.f);
        float bb1 = bias1[col + 1] + (bias2 ? bias2[col + 1] : 0.f);
        #pragma unroll
        for (int am = 0; am < 4; am++) {
            #pragma unroll
            for (int half = 0; half < 2; half++) {
                int row = rg + am * 16 + half * 8;
                float x0 = acc[am][bn][half * 2]     + bb0;
                float x1 = acc[am][bn][half * 2 + 1] + bb1;
                if (mode) {
                    x0 = x0 >= 0.f ? x0 : 0.01f * x0;
                    x1 = x1 >= 0.f ? x1 : 0.01f * x1;
                }
                size_t base = (size_t)row * Mout + col;
                if (mode <= 1) {
                    float2 v; v.x = x0; v.y = x1;
                    *(float2*)(Cf + base) = v;
                } else {
                    __nv_bfloat16 h0, l0, h1, l1;
                    split2(x0, h0, l0);
                    split2(x1, h1, l1);
                    __nv_bfloat162 ph, pl;
                    ph.x = h0; ph.y = h1;
                    pl.x = l0; pl.y = l1;
                    *(__nv_bfloat162*)(C2h + base) = ph;
                    *(__nv_bfloat162*)(C2l + base) = pl;
                }
            }
        }
    }
}

// ---------------- BiLSTM recurrence (fp32) ----------------
__global__ __launch_bounds__(512) void lstm_kernel() {
    int dir = blockIdx.y;
    int b0  = blockIdx.x * 8;
    const float* xg = dir ? g_xgb : g_xgf;
    const float* W4 = dir ? g_Whh4_b : g_Whh4_f;

    __shared__ float hs[8][Hz];
    __shared__ float cs[8][Hz];
    __shared__ float gb[8][G4];

    int g = threadIdx.x;
    for (int idx = g; idx < 8 * Hz; idx += 512) {
        ((float*)hs)[idx] = 0.f;
        ((float*)cs)[idx] = 0.f;
    }
    __syncthreads();

    for (int t = 0; t < Lz; t++) {
        int pos = dir ? (Lz - 1 - t) : t;
        float acc[8];
        #pragma unroll
        for (int r = 0; r < 8; r++)
            acc[r] = xg[((size_t)(b0 + r) * Lz + pos) * G4 + g];

        #pragma unroll 8
        for (int kc = 0; kc < Hz / 4; kc++) {
            float4 w = *(const float4*)(W4 + kc * (G4 * 4) + (g << 2));
            #pragma unroll
            for (int r = 0; r < 8; r++) {
                float4 hv = *(const float4*)(&hs[r][kc << 2]);
                acc[r] = fmaf(w.x, hv.x, acc[r]);
                acc[r] = fmaf(w.y, hv.y, acc[r]);
                acc[r] = fmaf(w.z, hv.z, acc[r]);
                acc[r] = fmaf(w.w, hv.w, acc[r]);
            }
        }
        #pragma unroll
        for (int r = 0; r < 8; r++) gb[r][g] = acc[r];
        __syncthreads();

        #pragma unroll
        for (int rep = 0; rep < 2; rep++) {
            int idx = rep * 512 + g;
            int r = idx >> 7, j = idx & 127;
            float xi = gb[r][j];
            float xf = gb[r][j + Hz];
            float xc = gb[r][j + 2 * Hz];
            float xo = gb[r][j + 3 * Hz];
            float ii = 1.f / (1.f + expf(-xi));
            float ff = 1.f / (1.f + expf(-xf));
            float gg = tanhf(xc);
            float oo = 1.f / (1.f + expf(-xo));
            float c  = ff * cs[r][j] + ii * gg;
            float h  = oo * tanhf(c);
            cs[r][j] = c;
            hs[r][j] = h;
            size_t o = ((size_t)(b0 + r) * Lz + pos) * Dz + dir * Hz + j;
            __nv_bfloat16 bh, bl;
            split2(h, bh, bl);
            g_Hh[o] = bh; g_Hl[o] = bl;
        }
        __syncthreads();
    }
}

// ---------------- tag projection ----------------
__global__ __launch_bounds__(256) void logits_kernel(
    const float* __restrict__ H2, const float* __restrict__ Wt, const float* __restrict__ bt)
{
    __shared__ float wts[Tz * Dz];
    __shared__ float bts[Tz];
    for (int i = threadIdx.x; i < Tz * Dz; i += 256) wts[i] = Wt[i];
    if (threadIdx.x < Tz) bts[threadIdx.x] = bt[threadIdx.x];
    __syncthreads();

    int n    = (blockIdx.x * 256 + threadIdx.x) >> 5;
    int lane = threadIdx.x & 31;
    if (n >= NL) return;
    float acc[Tz];
    #pragma unroll
    for (int t = 0; t < Tz; t++) acc[t] = 0.f;
    const float* hrow = H2 + (size_t)n * Dz;
    for (int k = lane; k < Dz; k += 32) {
        float x = hrow[k];
        #pragma unroll
        for (int t = 0; t < Tz; t++) acc[t] = fmaf(x, wts[t * Dz + k], acc[t]);
    }
    #pragma unroll
    for (int t = 0; t < Tz; t++)
        #pragma unroll
        for (int off = 16; off; off >>= 1)
            acc[t] += __shfl_xor_sync(0xffffffffu, acc[t], off);
    if (lane == 0) {
        #pragma unroll
        for (int t = 0; t < Tz; t++) {
            float x = acc[t] + bts[t];
            g_logits[(size_t)n * Tz + t] = (x >= 0.f ? x : 0.01f * x);
        }
    }
}

// ---------------- per-sample Viterbi ----------------
__global__ void viterbi_kernel(const float* __restrict__ trans,
                               float* __restrict__ out, int score_off, int path_off)
{
    __shared__ float tr[Tz * Tz];
    if (threadIdx.x < Tz * Tz) tr[threadIdx.x] = trans[threadIdx.x];
    __syncthreads();
    int b = blockIdx.x * blockDim.x + threadIdx.x;
    if (b >= Bz) return;

    const float* lg = g_logits + (size_t)b * Lz * Tz;
    float prev[Tz];
    #pragma unroll
    for (int t = 0; t < Tz; t++) prev[t] = lg[t];

    for (int l = 1; l < Lz; l++) {
        float cur[Tz];
        #pragma unroll
        for (int j = 0; j < Tz; j++) {
            float best = prev[0] + tr[j];
            int bi = 0;
            #pragma unroll
            for (int i = 1; i < Tz; i++) {
                float v = prev[i] + tr[i * Tz + j];
                if (v > best) { best = v; bi = i; }
            }
            g_bp[((size_t)b * Lz + l) * Tz + j] = (unsigned char)bi;
            cur[j] = lg[(size_t)l * Tz + j] + best;
        }
        #pragma unroll
        for (int j = 0; j < Tz; j++) prev[j] = cur[j];
    }
    float best = prev[0];
    int last = 0;
    #pragma unroll
    for (int i = 1; i < Tz; i++) if (prev[i] > best) { best = prev[i]; last = i; }

    if (score_off >= 0) out[score_off + b] = best;
    if (path_off >= 0) {
        int tag = last;
        out[path_off + (size_t)b * Lz + (Lz - 1)] = (float)tag;
        for (int l = Lz - 1; l >= 1; l--) {
            tag = g_bp[((size_t)b * Lz + l) * Tz + tag];
            out[path_off + (size_t)b * Lz + (l - 1)] = (float)tag;
        }
    }
}

// ---------------- launch ----------------
extern "C" void kernel_launch(void* const* d_in, const int* in_sizes, int n_in,
                              void* d_out, int out_size) {
    const int*   sent  = (const int*)d_in[0];
    const float* emb   = (const float*)d_in[2];
    const float* Wih_f = (const float*)d_in[3];
    const float* Whh_f = (const float*)d_in[4];
    const float* bih_f = (const float*)d_in[5];
    const float* bhh_f = (const float*)d_in[6];
    const float* Wih_b = (const float*)d_in[7];
    const float* Whh_b = (const float*)d_in[8];
    const float* bih_b = (const float*)d_in[9];
    const float* bhh_b = (const float*)d_in[10];
    const float* W1    = (const float*)d_in[11];
    const float* b1    = (const float*)d_in[12];
    const float* W2    = (const float*)d_in[13];
    const float* b2    = (const float*)d_in[14];
    const float* Wt    = (const float*)d_in[15];
    const float* bt    = (const float*)d_in[16];
    const float* trans = (const float*)d_in[17];
    float* out = (float*)d_out;

    float *X, *xgf, *xgb;
    __nv_bfloat16 *Xh, *Xl, *Hh, *Hl, *M1h, *M1l;
    __nv_bfloat16 *WFh, *WFl, *WBh, *WBl, *W1h, *W1l, *W2h, *W2l;
    cudaGetSymbolAddress((void**)&X,   g_X);
    cudaGetSymbolAddress((void**)&xgf, g_xgf);
    cudaGetSymbolAddress((void**)&xgb, g_xgb);
    cudaGetSymbolAddress((void**)&Xh, g_Xh);   cudaGetSymbolAddress((void**)&Xl, g_Xl);
    cudaGetSymbolAddress((void**)&Hh, g_Hh);   cudaGetSymbolAddress((void**)&Hl, g_Hl);
    cudaGetSymbolAddress((void**)&M1h, g_M1h); cudaGetSymbolAddress((void**)&M1l, g_M1l);
    cudaGetSymbolAddress((void**)&WFh, g_WFh); cudaGetSymbolAddress((void**)&WFl, g_WFl);
    cudaGetSymbolAddress((void**)&WBh, g_WBh); cudaGetSymbolAddress((void**)&WBl, g_WBl);
    cudaGetSymbolAddress((void**)&W1h, g_W1h); cudaGetSymbolAddress((void**)&W1l, g_W1l);
    cudaGetSymbolAddress((void**)&W2h, g_W2h); cudaGetSymbolAddress((void**)&W2l, g_W2l);

    cudaMemsetAsync(d_out, 0, (size_t)out_size * sizeof(float));

    // 1. gather + convert embeddings
    gather_conv<<<NL * (Ez / 4) / 256, 256>>>(sent, emb);
    // 2. convert weights, repack Whh
    conv2<<<(G4 * Ez + 255) / 256, 256>>>(Wih_f, WFh, WFl, G4 * Ez);
    conv2<<<(G4 * Ez + 255) / 256, 256>>>(Wih_b, WBh, WBl, G4 * Ez);
    conv2<<<(Dz * Dz + 255) / 256, 256>>>(W1, W1h, W1l, Dz * Dz);
    conv2<<<(Dz * Dz + 255) / 256, 256>>>(W2, W2h, W2l, Dz * Dz);
    prep_whh<<<(G4 * Hz + 255) / 256, 256>>>(Whh_f, Whh_b);
    // 3. input-gate GEMMs (HMMA split-bf16)
    gemm_mma<<<dim3(G4 / 128, NL / 128), 256>>>(
        Xh, Xl, WFh, WFl, bih_f, bhh_f, xgf, nullptr, nullptr, G4, 0);
    gemm_mma<<<dim3(G4 / 128, NL / 128), 256>>>(
        Xh, Xl, WBh, WBl, bih_b, bhh_b, xgb, nullptr, nullptr, G4, 0);
    // 4. BiLSTM recurrence (writes bf16 split2 hidden)
    lstm_kernel<<<dim3(Bz / 8, 2), 512>>>();
    // 5. MLP1 (split2 out) and MLP2 (fp32 out)
    gemm_mma<<<dim3(Dz / 128, NL / 128), 256>>>(
        Hh, Hl, W1h, W1l, b1, nullptr, nullptr, M1h, M1l, Dz, 2);
    gemm_mma<<<dim3(Dz / 128, NL / 128), 256>>>(
        M1h, M1l, W2h, W2l, b2, nullptr, X, nullptr, nullptr, Dz, 1);
    // 6. tag projection
    logits_kernel<<<NL / 8, 256>>>(X, Wt, bt);
    // 7. viterbi + output
    int score_off = -1, path_off = -1;
    if (out_size >= Bz * (Lz + 1))      { score_off = 0; path_off = Bz; }
    else if (out_size >= Bz * Lz)       { path_off = 0; }
    else                                { score_off = 0; }
    viterbi_kernel<<<(Bz + 255) / 256, 256>>>(trans, out, score_off, path_off);
}

// round 6
// speedup vs baseline: 1.5137x; 1.1496x over previous
#include <cuda_runtime.h>
#include <cuda_bf16.h>
#include <cstdint>
#include <math.h>

#define Bz 512
#define Lz 200
#define Ez 256
#define Hz 128
#define G4 512          // 4*H
#define Dz 256
#define Tz 6
#define NL (Bz*Lz)      // 102400

typedef unsigned long long u64t;

// ---------------- device scratch ----------------
__device__ float g_X[NL*Dz];          // h2 (MLP2 fp32 output)
__device__ float g_xgf[NL*G4];        // forward input gates (fp32)
__device__ float g_xgb[NL*G4];        // backward input gates (fp32)
__device__ float g_logits[NL*Tz];
__device__ float g_Whh4_f[Hz*G4];
__device__ float g_Whh4_b[Hz*G4];
__device__ unsigned char g_bp[Bz*Lz*Tz];

// bf16 split-2 operand buffers (value = hi + lo)
__device__ __nv_bfloat16 g_Xh[NL*Ez],  g_Xl[NL*Ez];     // embeddings
__device__ __nv_bfloat16 g_Hh[NL*Dz],  g_Hl[NL*Dz];     // BiLSTM hidden
__device__ __nv_bfloat16 g_M1h[NL*Dz], g_M1l[NL*Dz];    // MLP1 out
__device__ __nv_bfloat16 g_WFh[G4*Ez], g_WFl[G4*Ez];    // Wih_f
__device__ __nv_bfloat16 g_WBh[G4*Ez], g_WBl[G4*Ez];    // Wih_b
__device__ __nv_bfloat16 g_W1h[Dz*Dz], g_W1l[Dz*Dz];
__device__ __nv_bfloat16 g_W2h[Dz*Dz], g_W2l[Dz*Dz];

// ================= helpers =================
__device__ __forceinline__ uint32_t smem_u32(const void* p) {
    uint32_t a;
    asm("{ .reg .u64 t; cvta.to.shared.u64 t, %1; cvt.u32.u64 %0, t; }" : "=r"(a) : "l"(p));
    return a;
}
__device__ __forceinline__ uint32_t swz(uint32_t off) {        // SW128-style XOR swizzle
    return off ^ ((off >> 3) & 0x70);
}
__device__ __forceinline__ void ldm4(uint32_t* r, uint32_t addr) {
    asm volatile("ldmatrix.sync.aligned.m8n8.x4.shared.b16 {%0,%1,%2,%3}, [%4];"
        : "=r"(r[0]), "=r"(r[1]), "=r"(r[2]), "=r"(r[3]) : "r"(addr));
}
__device__ __forceinline__ void mma16816(float* d, const uint32_t* a, const uint32_t* b) {
    asm volatile("mma.sync.aligned.m16n8k16.row.col.f32.bf16.bf16.f32 "
        "{%0,%1,%2,%3}, {%4,%5,%6,%7}, {%8,%9}, {%0,%1,%2,%3};"
        : "+f"(d[0]), "+f"(d[1]), "+f"(d[2]), "+f"(d[3])
        : "r"(a[0]), "r"(a[1]), "r"(a[2]), "r"(a[3]), "r"(b[0]), "r"(b[1]));
}
__device__ __forceinline__ void split2(float x, __nv_bfloat16& h, __nv_bfloat16& l) {
    h = __float2bfloat16(x);
    l = __float2bfloat16(x - __bfloat162float(h));
}
// packed f32x2 FMA (Blackwell)
__device__ __forceinline__ u64t fma2(u64t a, u64t b, u64t c) {
    u64t d;
    asm("fma.rn.f32x2 %0, %1, %2, %3;" : "=l"(d) : "l"(a), "l"(b), "l"(c));
    return d;
}
__device__ __forceinline__ u64t pack2(float x, float y) {
    u64t r; asm("mov.b64 %0, {%1, %2};" : "=l"(r) : "f"(x), "f"(y)); return r;
}
__device__ __forceinline__ float hadd2(u64t v) {
    float x, y;
    asm("mov.b64 {%0, %1}, %2;" : "=f"(x), "=f"(y) : "l"(v));
    return x + y;
}
__device__ __forceinline__ void ldg_w2(const float* p, u64t& a, u64t& b) {
    asm("ld.global.nc.L1::evict_last.v2.u64 {%0,%1}, [%2];" : "=l"(a), "=l"(b) : "l"(p));
}
__device__ __forceinline__ void lds_h2(uint32_t addr, u64t& a, u64t& b) {
    asm("ld.shared.v2.u64 {%0,%1}, [%2];" : "=l"(a), "=l"(b) : "r"(addr));
}

// ---------------- gather embeddings -> bf16 split2 ----------------
__global__ void gather_conv(const int* __restrict__ sent, const float* __restrict__ emb) {
    int idx = blockIdx.x * 256 + threadIdx.x;     // float4 units over NL x 256
    if (idx >= NL * (Ez / 4)) return;
    int n = idx >> 6, e4 = idx & 63;
    int tok = sent[n];
    float4 v = ((const float4*)emb)[(size_t)tok * 64 + e4];
    size_t o = (size_t)idx * 4;
    float vv[4] = {v.x, v.y, v.z, v.w};
    __nv_bfloat16 hh[4], ll[4];
    #pragma unroll
    for (int k = 0; k < 4; k++) split2(vv[k], hh[k], ll[k]);
    __nv_bfloat162 p;
    p.x = hh[0]; p.y = hh[1]; ((__nv_bfloat162*)(g_Xh + o))[0] = p;
    p.x = hh[2]; p.y = hh[3]; ((__nv_bfloat162*)(g_Xh + o))[1] = p;
    p.x = ll[0]; p.y = ll[1]; ((__nv_bfloat162*)(g_Xl + o))[0] = p;
    p.x = ll[2]; p.y = ll[3]; ((__nv_bfloat162*)(g_Xl + o))[1] = p;
}

// ---------------- fp32 -> split2 ----------------
__global__ void conv2(const float* __restrict__ src, __nv_bfloat16* __restrict__ hi,
                      __nv_bfloat16* __restrict__ lo, int n) {
    int i = blockIdx.x * 256 + threadIdx.x;
    if (i >= n) return;
    __nv_bfloat16 h, l;
    split2(src[i], h, l);
    hi[i] = h; lo[i] = l;
}

// ---------------- repack Whh ----------------
__global__ void prep_whh(const float* __restrict__ Whh_f, const float* __restrict__ Whh_b) {
    int idx = blockIdx.x * 256 + threadIdx.x;
    if (idx >= G4 * Hz) return;
    int g = idx / Hz, k = idx % Hz;
    int dst = (k >> 2) * (G4 * 4) + g * 4 + (k & 3);
    g_Whh4_f[dst] = Whh_f[idx];
    g_Whh4_b[dst] = Whh_b[idx];
}

// ================= HMMA split-bf16 GEMM =================
// C[NL rows, Mout cols] = A[.,256] @ B[Mout,256]^T + bias ; A,B given as (hi,lo) bf16 pairs.
// mode 0: fp32 out, bias1+bias2, no act
// mode 1: fp32 out, bias1, leaky
// mode 2: bf16 split2 out, bias1, leaky
__global__ __launch_bounds__(256) void gemm_mma(
    const __nv_bfloat16* __restrict__ Ah, const __nv_bfloat16* __restrict__ Al,
    const __nv_bfloat16* __restrict__ Bh, const __nv_bfloat16* __restrict__ Bl,
    const float* __restrict__ bias1, const float* __restrict__ bias2,
    float* __restrict__ Cf,
    __nv_bfloat16* __restrict__ C2h, __nv_bfloat16* __restrict__ C2l,
    int Mout, int mode)
{
    __shared__ __align__(1024) char sm[32768];
    char* smA = sm;
    char* smB = sm + 16384;
    uint32_t sA = smem_u32(smA), sB = smem_u32(smB);

    int tid = threadIdx.x, wid = tid >> 5, lane = tid & 31;
    int row0 = blockIdx.y * 128;
    int col0 = blockIdx.x * 128;
    int wm0 = (wid & 1) * 64;        // warp M offset within tile
    int wn0 = (wid >> 1) * 32;       // warp N offset within tile

    float acc[4][4][4];
    #pragma unroll
    for (int i = 0; i < 4; i++)
        #pragma unroll
        for (int j = 0; j < 4; j++)
            #pragma unroll
            for (int k = 0; k < 4; k++) acc[i][j][k] = 0.f;

    // ldmatrix per-lane addressing pieces
    int arow = ((lane >> 3) & 1) * 8 + (lane & 7);       // + am*16
    int acb  = (lane >> 4) << 4;                         // + ks*32 (+64 for lo)
    int brow = ((lane >> 4) << 3) + (lane & 7);          // + np*16
    int bcb  = ((lane >> 3) & 1) << 4;                   // + ks*32 (+64 for lo)

    for (int kc = 0; kc < 8; kc++) {
        int k0 = kc * 32;
        __syncthreads();
        #pragma unroll
        for (int j = 0; j < 4; j++) {
            int idx = tid + j * 256;           // 0..1023
            int r = idx >> 3, s = idx & 7;     // s<4: hi seg, s>=4: lo seg
            const __nv_bfloat16* src = (s < 4 ? Ah : Al) + (size_t)(row0 + r) * 256 + k0 + (s & 3) * 8;
            *(uint4*)(smA + swz(r * 128 + s * 16)) = *(const uint4*)src;
        }
        #pragma unroll
        for (int j = 0; j < 4; j++) {
            int idx = tid + j * 256;
            int r = idx >> 3, s = idx & 7;
            const __nv_bfloat16* src = (s < 4 ? Bh : Bl) + (size_t)(col0 + r) * 256 + k0 + (s & 3) * 8;
            *(uint4*)(smB + swz(r * 128 + s * 16)) = *(const uint4*)src;
        }
        __syncthreads();

        #pragma unroll
        for (int ks = 0; ks < 2; ks++) {
            uint32_t aH[4][4], aL[4][4], bH[2][4], bL[2][4];
            #pragma unroll
            for (int am = 0; am < 4; am++) {
                int r = wm0 + am * 16 + arow;
                ldm4(aH[am], sA + swz((uint32_t)(r * 128 + ks * 32 + acb)));
                ldm4(aL[am], sA + swz((uint32_t)(r * 128 + 64 + ks * 32 + acb)));
            }
            #pragma unroll
            for (int np = 0; np < 2; np++) {
                int r = wn0 + np * 16 + brow;
                ldm4(bH[np], sB + swz((uint32_t)(r * 128 + ks * 32 + bcb)));
                ldm4(bL[np], sB + swz((uint32_t)(r * 128 + 64 + ks * 32 + bcb)));
            }
            #pragma unroll
            for (int am = 0; am < 4; am++) {
                #pragma unroll
                for (int bn = 0; bn < 4; bn++) {
                    const uint32_t* bh = &bH[bn >> 1][(bn & 1) * 2];
                    const uint32_t* bl = &bL[bn >> 1][(bn & 1) * 2];
                    mma16816(acc[am][bn], aH[am], bh);   // Ah*Bh
                    mma16816(acc[am][bn], aH[am], bl);   // Ah*Bl
                    mma16816(acc[am][bn], aL[am], bh);   // Al*Bh
                }
            }
        }
    }

    // ---------------- epilogue ----------------
    int rg = row0 + wm0 + (lane >> 2);          // + am*16 (+8)
    int cg = col0 + wn0 + (lane & 3) * 2;       // + bn*8
    #pragma unroll
    for (int bn = 0; bn < 4; bn++) {
        int col = cg + bn * 8;
        float bb0 = bias1[col]     + (bias2 ? bias2[col]     : 0.f);
        float bb1 = bias1[col + 1] + (bias2 ? bias2[col + 1] : 0.f);
        #pragma unroll
        for (int am = 0; am < 4; am++) {
            #pragma unroll
            for (int half = 0; half < 2; half++) {
                int row = rg + am * 16 + half * 8;
                float x0 = acc[am][bn][half * 2]     + bb0;
                float x1 = acc[am][bn][half * 2 + 1] + bb1;
                if (mode) {
                    x0 = x0 >= 0.f ? x0 : 0.01f * x0;
                    x1 = x1 >= 0.f ? x1 : 0.01f * x1;
                }
                size_t base = (size_t)row * Mout + col;
                if (mode <= 1) {
                    float2 v; v.x = x0; v.y = x1;
                    *(float2*)(Cf + base) = v;
                } else {
                    __nv_bfloat16 h0, l0, h1, l1;
                    split2(x0, h0, l0);
                    split2(x1, h1, l1);
                    __nv_bfloat162 ph, pl;
                    ph.x = h0; ph.y = h1;
                    pl.x = l0; pl.y = l1;
                    *(__nv_bfloat162*)(C2h + base) = ph;
                    *(__nv_bfloat162*)(C2l + base) = pl;
                }
            }
        }
    }
}

// ---------------- BiLSTM recurrence (fp32, packed f32x2 FMA) ----------------
// grid = (Bz/8, 2 dirs), block = 512 threads (one per gate g).
// acc2[r] holds (sum over even k, sum over odd k) packed; horizontal add at end.
__global__ __launch_bounds__(512) void lstm_kernel() {
    int dir = blockIdx.y;
    int b0  = blockIdx.x * 8;
    const float* xg = dir ? g_xgb : g_xgf;
    const float* W4 = dir ? g_Whh4_b : g_Whh4_f;

    __shared__ float hs[8][Hz];
    __shared__ float cs[8][Hz];
    __shared__ float gb[8][G4];

    int g = threadIdx.x;
    uint32_t hs_base = smem_u32(&hs[0][0]);
    for (int idx = g; idx < 8 * Hz; idx += 512) {
        ((float*)hs)[idx] = 0.f;
        ((float*)cs)[idx] = 0.f;
    }
    __syncthreads();

    const float* wptr0 = W4 + (g << 2);

    for (int t = 0; t < Lz; t++) {
        int pos = dir ? (Lz - 1 - t) : t;
        u64t acc[8];
        #pragma unroll
        for (int r = 0; r < 8; r++)
            acc[r] = pack2(xg[((size_t)(b0 + r) * Lz + pos) * G4 + g], 0.f);

        #pragma unroll 8
        for (int kc = 0; kc < Hz / 4; kc++) {
            u64t w01, w23;
            ldg_w2(wptr0 + kc * (G4 * 4), w01, w23);   // (w_k,w_k+1),(w_k+2,w_k+3)
            #pragma unroll
            for (int r = 0; r < 8; r++) {
                u64t h01, h23;
                lds_h2(hs_base + (uint32_t)(r * Hz + (kc << 2)) * 4u, h01, h23);
                acc[r] = fma2(w01, h01, acc[r]);
                acc[r] = fma2(w23, h23, acc[r]);
            }
        }
        #pragma unroll
        for (int r = 0; r < 8; r++) gb[r][g] = hadd2(acc[r]);
        __syncthreads();

        #pragma unroll
        for (int rep = 0; rep < 2; rep++) {
            int idx = rep * 512 + g;
            int r = idx >> 7, j = idx & 127;
            float xi = gb[r][j];
            float xf = gb[r][j + Hz];
            float xc = gb[r][j + 2 * Hz];
            float xo = gb[r][j + 3 * Hz];
            float ii = 1.f / (1.f + expf(-xi));
            float ff = 1.f / (1.f + expf(-xf));
            float gg = tanhf(xc);
            float oo = 1.f / (1.f + expf(-xo));
            float c  = ff * cs[r][j] + ii * gg;
            float h  = oo * tanhf(c);
            cs[r][j] = c;
            hs[r][j] = h;
            size_t o = ((size_t)(b0 + r) * Lz + pos) * Dz + dir * Hz + j;
            __nv_bfloat16 bh, bl;
            split2(h, bh, bl);
            g_Hh[o] = bh; g_Hl[o] = bl;
        }
        __syncthreads();
    }
}

// ---------------- tag projection ----------------
__global__ __launch_bounds__(256) void logits_kernel(
    const float* __restrict__ H2, const float* __restrict__ Wt, const float* __restrict__ bt)
{
    __shared__ float wts[Tz * Dz];
    __shared__ float bts[Tz];
    for (int i = threadIdx.x; i < Tz * Dz; i += 256) wts[i] = Wt[i];
    if (threadIdx.x < Tz) bts[threadIdx.x] = bt[threadIdx.x];
    __syncthreads();

    int n    = (blockIdx.x * 256 + threadIdx.x) >> 5;
    int lane = threadIdx.x & 31;
    if (n >= NL) return;
    float acc[Tz];
    #pragma unroll
    for (int t = 0; t < Tz; t++) acc[t] = 0.f;
    const float* hrow = H2 + (size_t)n * Dz;
    for (int k = lane; k < Dz; k += 32) {
        float x = hrow[k];
        #pragma unroll
        for (int t = 0; t < Tz; t++) acc[t] = fmaf(x, wts[t * Dz + k], acc[t]);
    }
    #pragma unroll
    for (int t = 0; t < Tz; t++)
        #pragma unroll
        for (int off = 16; off; off >>= 1)
            acc[t] += __shfl_xor_sync(0xffffffffu, acc[t], off);
    if (lane == 0) {
        #pragma unroll
        for (int t = 0; t < Tz; t++) {
            float x = acc[t] + bts[t];
            g_logits[(size_t)n * Tz + t] = (x >= 0.f ? x : 0.01f * x);
        }
    }
}

// ---------------- per-sample Viterbi ----------------
__global__ void viterbi_kernel(const float* __restrict__ trans,
                               float* __restrict__ out, int score_off, int path_off)
{
    __shared__ float tr[Tz * Tz];
    if (threadIdx.x < Tz * Tz) tr[threadIdx.x] = trans[threadIdx.x];
    __syncthreads();
    int b = blockIdx.x * blockDim.x + threadIdx.x;
    if (b >= Bz) return;

    const float* lg = g_logits + (size_t)b * Lz * Tz;
    float prev[Tz];
    #pragma unroll
    for (int t = 0; t < Tz; t++) prev[t] = lg[t];

    for (int l = 1; l < Lz; l++) {
        float cur[Tz];
        #pragma unroll
        for (int j = 0; j < Tz; j++) {
            float best = prev[0] + tr[j];
            int bi = 0;
            #pragma unroll
            for (int i = 1; i < Tz; i++) {
                float v = prev[i] + tr[i * Tz + j];
                if (v > best) { best = v; bi = i; }
            }
            g_bp[((size_t)b * Lz + l) * Tz + j] = (unsigned char)bi;
            cur[j] = lg[(size_t)l * Tz + j] + best;
        }
        #pragma unroll
        for (int j = 0; j < Tz; j++) prev[j] = cur[j];
    }
    float best = prev[0];
    int last = 0;
    #pragma unroll
    for (int i = 1; i < Tz; i++) if (prev[i] > best) { best = prev[i]; last = i; }

    if (score_off >= 0) out[score_off + b] = best;
    if (path_off >= 0) {
        int tag = last;
        out[path_off + (size_t)b * Lz + (Lz - 1)] = (float)tag;
        for (int l = Lz - 1; l >= 1; l--) {
            tag = g_bp[((size_t)b * Lz + l) * Tz + tag];
            out[path_off + (size_t)b * Lz + (l - 1)] = (float)tag;
        }
    }
}

// ---------------- launch ----------------
extern "C" void kernel_launch(void* const* d_in, const int* in_sizes, int n_in,
                              void* d_out, int out_size) {
    const int*   sent  = (const int*)d_in[0];
    const float* emb   = (const float*)d_in[2];
    const float* Wih_f = (const float*)d_in[3];
    const float* Whh_f = (const float*)d_in[4];
    const float* bih_f = (const float*)d_in[5];
    const float* bhh_f = (const float*)d_in[6];
    const float* Wih_b = (const float*)d_in[7];
    const float* Whh_b = (const float*)d_in[8];
    const float* bih_b = (const float*)d_in[9];
    const float* bhh_b = (const float*)d_in[10];
    const float* W1    = (const float*)d_in[11];
    const float* b1    = (const float*)d_in[12];
    const float* W2    = (const float*)d_in[13];
    const float* b2    = (const float*)d_in[14];
    const float* Wt    = (const float*)d_in[15];
    const float* bt    = (const float*)d_in[16];
    const float* trans = (const float*)d_in[17];
    float* out = (float*)d_out;

    float *X, *xgf, *xgb;
    __nv_bfloat16 *Xh, *Xl, *Hh, *Hl, *M1h, *M1l;
    __nv_bfloat16 *WFh, *WFl, *WBh, *WBl, *W1h, *W1l, *W2h, *W2l;
    cudaGetSymbolAddress((void**)&X,   g_X);
    cudaGetSymbolAddress((void**)&xgf, g_xgf);
    cudaGetSymbolAddress((void**)&xgb, g_xgb);
    cudaGetSymbolAddress((void**)&Xh, g_Xh);   cudaGetSymbolAddress((void**)&Xl, g_Xl);
    cudaGetSymbolAddress((void**)&Hh, g_Hh);   cudaGetSymbolAddress((void**)&Hl, g_Hl);
    cudaGetSymbolAddress((void**)&M1h, g_M1h); cudaGetSymbolAddress((void**)&M1l, g_M1l);
    cudaGetSymbolAddress((void**)&WFh, g_WFh); cudaGetSymbolAddress((void**)&WFl, g_WFl);
    cudaGetSymbolAddress((void**)&WBh, g_WBh); cudaGetSymbolAddress((void**)&WBl, g_WBl);
    cudaGetSymbolAddress((void**)&W1h, g_W1h); cudaGetSymbolAddress((void**)&W1l, g_W1l);
    cudaGetSymbolAddress((void**)&W2h, g_W2h); cudaGetSymbolAddress((void**)&W2l, g_W2l);

    cudaMemsetAsync(d_out, 0, (size_t)out_size * sizeof(float));

    // 1. gather + convert embeddings
    gather_conv<<<NL * (Ez / 4) / 256, 256>>>(sent, emb);
    // 2. convert weights, repack Whh
    conv2<<<(G4 * Ez + 255) / 256, 256>>>(Wih_f, WFh, WFl, G4 * Ez);
    conv2<<<(G4 * Ez + 255) / 256, 256>>>(Wih_b, WBh, WBl, G4 * Ez);
    conv2<<<(Dz * Dz + 255) / 256, 256>>>(W1, W1h, W1l, Dz * Dz);
    conv2<<<(Dz * Dz + 255) / 256, 256>>>(W2, W2h, W2l, Dz * Dz);
    prep_whh<<<(G4 * Hz + 255) / 256, 256>>>(Whh_f, Whh_b);
    // 3. input-gate GEMMs (HMMA split-bf16)
    gemm_mma<<<dim3(G4 / 128, NL / 128), 256>>>(
        Xh, Xl, WFh, WFl, bih_f, bhh_f, xgf, nullptr, nullptr, G4, 0);
    gemm_mma<<<dim3(G4 / 128, NL / 128), 256>>>(
        Xh, Xl, WBh, WBl, bih_b, bhh_b, xgb, nullptr, nullptr, G4, 0);
    // 4. BiLSTM recurrence (f32x2 packed FMA, writes bf16 split2 hidden)
    lstm_kernel<<<dim3(Bz / 8, 2), 512>>>();
    // 5. MLP1 (split2 out) and MLP2 (fp32 out)
    gemm_mma<<<dim3(Dz / 128, NL / 128), 256>>>(
        Hh, Hl, W1h, W1l, b1, nullptr, nullptr, M1h, M1l, Dz, 2);
    gemm_mma<<<dim3(Dz / 128, NL / 128), 256>>>(
        M1h, M1l, W2h, W2l, b2, nullptr, X, nullptr, nullptr, Dz, 1);
    // 6. tag projection
    logits_kernel<<<NL / 8, 256>>>(X, Wt, bt);
    // 7. viterbi + output
    int score_off = -1, path_off = -1;
    if (out_size >= Bz * (Lz + 1))      { score_off = 0; path_off = Bz; }
    else if (out_size >= Bz * Lz)       { path_off = 0; }
    else                                { score_off = 0; }
    viterbi_kernel<<<(Bz + 255) / 256, 256>>>(trans, out, score_off, path_off);
}

// round 9
// speedup vs baseline: 1.7947x; 1.1857x over previous
#include <cuda_runtime.h>
#include <cuda_bf16.h>
#include <cstdint>
#include <math.h>

#define Bz 512
#define Lz 200
#define Ez 256
#define Hz 128
#define G4 512          // 4*H
#define Dz 256
#define Tz 6
#define NL (Bz*Lz)      // 102400

typedef unsigned long long u64t;

// ---------------- device scratch ----------------
__device__ float g_X[NL*Dz];          // h2 (MLP2 fp32 output)
__device__ float g_xgf[NL*G4];        // forward input gates (fp32)
__device__ float g_xgb[NL*G4];        // backward input gates (fp32)
__device__ float g_logits[NL*Tz];     // emissions, TRANSPOSED layout [L][B][T]
__device__ float g_Whh4_f[Hz*G4];
__device__ float g_Whh4_b[Hz*G4];

// bf16 split-2 operand buffers (value = hi + lo)
__device__ __nv_bfloat16 g_Xh[NL*Ez],  g_Xl[NL*Ez];     // embeddings
__device__ __nv_bfloat16 g_Hh[NL*Dz],  g_Hl[NL*Dz];     // BiLSTM hidden
__device__ __nv_bfloat16 g_M1h[NL*Dz], g_M1l[NL*Dz];    // MLP1 out
__device__ __nv_bfloat16 g_WFh[G4*Ez], g_WFl[G4*Ez];    // Wih_f
__device__ __nv_bfloat16 g_WBh[G4*Ez], g_WBl[G4*Ez];    // Wih_b
__device__ __nv_bfloat16 g_W1h[Dz*Dz], g_W1l[Dz*Dz];
__device__ __nv_bfloat16 g_W2h[Dz*Dz], g_W2l[Dz*Dz];

// ================= helpers =================
__device__ __forceinline__ uint32_t smem_u32(const void* p) {
    uint32_t a;
    asm("{ .reg .u64 t; cvta.to.shared.u64 t, %1; cvt.u32.u64 %0, t; }" : "=r"(a) : "l"(p));
    return a;
}
__device__ __forceinline__ uint32_t swz(uint32_t off) {        // SW128-style XOR swizzle
    return off ^ ((off >> 3) & 0x70);
}
__device__ __forceinline__ void ldm4(uint32_t* r, uint32_t addr) {
    asm volatile("ldmatrix.sync.aligned.m8n8.x4.shared.b16 {%0,%1,%2,%3}, [%4];"
        : "=r"(r[0]), "=r"(r[1]), "=r"(r[2]), "=r"(r[3]) : "r"(addr));
}
__device__ __forceinline__ void mma16816(float* d, const uint32_t* a, const uint32_t* b) {
    asm volatile("mma.sync.aligned.m16n8k16.row.col.f32.bf16.bf16.f32 "
        "{%0,%1,%2,%3}, {%4,%5,%6,%7}, {%8,%9}, {%0,%1,%2,%3};"
        : "+f"(d[0]), "+f"(d[1]), "+f"(d[2]), "+f"(d[3])
        : "r"(a[0]), "r"(a[1]), "r"(a[2]), "r"(a[3]), "r"(b[0]), "r"(b[1]));
}
__device__ __forceinline__ void split2(float x, __nv_bfloat16& h, __nv_bfloat16& l) {
    h = __float2bfloat16(x);
    l = __float2bfloat16(x - __bfloat162float(h));
}
__device__ __forceinline__ void cp16(uint32_t dst, const void* src) {
    asm volatile("cp.async.cg.shared.global [%0], [%1], 16;" :: "r"(dst), "l"(src));
}
// packed f32x2 FMA (Blackwell)
__device__ __forceinline__ u64t fma2(u64t a, u64t b, u64t c) {
    u64t d;
    asm("fma.rn.f32x2 %0, %1, %2, %3;" : "=l"(d) : "l"(a), "l"(b), "l"(c));
    return d;
}
__device__ __forceinline__ u64t pack2(float x, float y) {
    u64t r; asm("mov.b64 %0, {%1, %2};" : "=l"(r) : "f"(x), "f"(y)); return r;
}
__device__ __forceinline__ float hadd2(u64t v) {
    float x, y;
    asm("mov.b64 {%0, %1}, %2;" : "=f"(x), "=f"(y) : "l"(v));
    return x + y;
}
__device__ __forceinline__ void ldg_w2(const float* p, u64t& a, u64t& b) {
    asm("ld.global.nc.L1::evict_last.v2.u64 {%0,%1}, [%2];" : "=l"(a), "=l"(b) : "l"(p));
}
__device__ __forceinline__ void lds_h2(uint32_t addr, u64t& a, u64t& b) {
    asm("ld.shared.v2.u64 {%0,%1}, [%2];" : "=l"(a), "=l"(b) : "r"(addr));
}

// ---------------- gather embeddings -> bf16 split2 ----------------
__global__ void gather_conv(const int* __restrict__ sent, const float* __restrict__ emb) {
    int idx = blockIdx.x * 256 + threadIdx.x;     // float4 units over NL x 256
    if (idx >= NL * (Ez / 4)) return;
    int n = idx >> 6, e4 = idx & 63;
    int tok = sent[n];
    float4 v = ((const float4*)emb)[(size_t)tok * 64 + e4];
    size_t o = (size_t)idx * 4;
    float vv[4] = {v.x, v.y, v.z, v.w};
    __nv_bfloat16 hh[4], ll[4];
    #pragma unroll
    for (int k = 0; k < 4; k++) split2(vv[k], hh[k], ll[k]);
    __nv_bfloat162 p;
    p.x = hh[0]; p.y = hh[1]; ((__nv_bfloat162*)(g_Xh + o))[0] = p;
    p.x = hh[2]; p.y = hh[3]; ((__nv_bfloat162*)(g_Xh + o))[1] = p;
    p.x = ll[0]; p.y = ll[1]; ((__nv_bfloat162*)(g_Xl + o))[0] = p;
    p.x = ll[2]; p.y = ll[3]; ((__nv_bfloat162*)(g_Xl + o))[1] = p;
}

// ---------------- fp32 -> split2 ----------------
__global__ void conv2(const float* __restrict__ src, __nv_bfloat16* __restrict__ hi,
                      __nv_bfloat16* __restrict__ lo, int n) {
    int i = blockIdx.x * 256 + threadIdx.x;
    if (i >= n) return;
    __nv_bfloat16 h, l;
    split2(src[i], h, l);
    hi[i] = h; lo[i] = l;
}

// ---------------- repack Whh ----------------
__global__ void prep_whh(const float* __restrict__ Whh_f, const float* __restrict__ Whh_b) {
    int idx = blockIdx.x * 256 + threadIdx.x;
    if (idx >= G4 * Hz) return;
    int g = idx / Hz, k = idx % Hz;
    int dst = (k >> 2) * (G4 * 4) + g * 4 + (k & 3);
    g_Whh4_f[dst] = Whh_f[idx];
    g_Whh4_b[dst] = Whh_b[idx];
}

// ================= HMMA split-bf16 GEMM (cp.async double-buffered) =================
// C[NL rows, Mout cols] = A[.,256] @ B[Mout,256]^T + bias ; A,B given as (hi,lo) bf16 pairs.
// mode 0: fp32 out, bias1+bias2, no act
// mode 1: fp32 out, bias1, leaky
// mode 2: bf16 split2 out, bias1, leaky
#define GEMM_SMEM 65536
__global__ __launch_bounds__(256) void gemm_mma(
    const __nv_bfloat16* __restrict__ Ah, const __nv_bfloat16* __restrict__ Al,
    const __nv_bfloat16* __restrict__ Bh, const __nv_bfloat16* __restrict__ Bl,
    const float* __restrict__ bias1, const float* __restrict__ bias2,
    float* __restrict__ Cf,
    __nv_bfloat16* __restrict__ C2h, __nv_bfloat16* __restrict__ C2l,
    int Mout, int mode)
{
    extern __shared__ __align__(1024) char dynsm[];
    uint32_t smem_base = smem_u32(dynsm);

    int tid = threadIdx.x, wid = tid >> 5, lane = tid & 31;
    int row0 = blockIdx.y * 128;
    int col0 = blockIdx.x * 128;
    int wm0 = (wid & 1) * 64;        // warp M offset within tile
    int wn0 = (wid >> 1) * 32;       // warp N offset within tile

    float acc[4][4][4];
    #pragma unroll
    for (int i = 0; i < 4; i++)
        #pragma unroll
        for (int j = 0; j < 4; j++)
            #pragma unroll
            for (int k = 0; k < 4; k++) acc[i][j][k] = 0.f;

    // ldmatrix per-lane addressing pieces
    int arow = ((lane >> 3) & 1) * 8 + (lane & 7);       // + am*16
    int acb  = (lane >> 4) << 4;                         // + ks*32 (+64 for lo)
    int brow = ((lane >> 4) << 3) + (lane & 7);          // + np*16
    int bcb  = ((lane >> 3) & 1) << 4;                   // + ks*32 (+64 for lo)

#define LOAD_CHUNK(kcv, bufi) do {                                                      \
        int k0_ = (kcv) * 32;                                                           \
        uint32_t sb_ = smem_base + (bufi) * 32768;                                      \
        _Pragma("unroll")                                                               \
        for (int j_ = 0; j_ < 4; j_++) {                                                \
            int idx_ = tid + j_ * 256;                                                  \
            int r_ = idx_ >> 3, s_ = idx_ & 7;                                          \
            const __nv_bfloat16* pa_ = (s_ < 4 ? Ah : Al) + (size_t)(row0 + r_) * 256 + k0_ + (s_ & 3) * 8; \
            cp16(sb_ + swz(r_ * 128 + s_ * 16), pa_);                                   \
            const __nv_bfloat16* pb_ = (s_ < 4 ? Bh : Bl) + (size_t)(col0 + r_) * 256 + k0_ + (s_ & 3) * 8; \
            cp16(sb_ + 16384 + swz(r_ * 128 + s_ * 16), pb_);                           \
        }                                                                               \
        asm volatile("cp.async.commit_group;" ::: "memory");                            \
    } while (0)

    LOAD_CHUNK(0, 0);

    for (int kc = 0; kc < 8; kc++) {
        if (kc < 7) {
            LOAD_CHUNK(kc + 1, (kc + 1) & 1);
            asm volatile("cp.async.wait_group 1;" ::: "memory");
        } else {
            asm volatile("cp.async.wait_group 0;" ::: "memory");
        }
        __syncthreads();

        uint32_t sA = smem_base + (kc & 1) * 32768;
        uint32_t sB = sA + 16384;

        #pragma unroll
        for (int ks = 0; ks < 2; ks++) {
            uint32_t aH[4][4], aL[4][4], bH[2][4], bL[2][4];
            #pragma unroll
            for (int am = 0; am < 4; am++) {
                int r = wm0 + am * 16 + arow;
                ldm4(aH[am], sA + swz((uint32_t)(r * 128 + ks * 32 + acb)));
                ldm4(aL[am], sA + swz((uint32_t)(r * 128 + 64 + ks * 32 + acb)));
            }
            #pragma unroll
            for (int np = 0; np < 2; np++) {
                int r = wn0 + np * 16 + brow;
                ldm4(bH[np], sB + swz((uint32_t)(r * 128 + ks * 32 + bcb)));
                ldm4(bL[np], sB + swz((uint32_t)(r * 128 + 64 + ks * 32 + bcb)));
            }
            #pragma unroll
            for (int am = 0; am < 4; am++) {
                #pragma unroll
                for (int bn = 0; bn < 4; bn++) {
                    const uint32_t* bh = &bH[bn >> 1][(bn & 1) * 2];
                    const uint32_t* bl = &bL[bn >> 1][(bn & 1) * 2];
                    mma16816(acc[am][bn], aH[am], bh);   // Ah*Bh
                    mma16816(acc[am][bn], aH[am], bl);   // Ah*Bl
                    mma16816(acc[am][bn], aL[am], bh);   // Al*Bh
                }
            }
        }
        __syncthreads();
    }
#undef LOAD_CHUNK

    // ---------------- epilogue ----------------
    int rg = row0 + wm0 + (lane >> 2);          // + am*16 (+8)
    int cg = col0 + wn0 + (lane & 3) * 2;       // + bn*8
    #pragma unroll
    for (int bn = 0; bn < 4; bn++) {
        int col = cg + bn * 8;
        float bb0 = bias1[col]     + (bias2 ? bias2[col]     : 0.f);
        float bb1 = bias1[col + 1] + (bias2 ? bias2[col + 1] : 0.f);
        #pragma unroll
        for (int am = 0; am < 4; am++) {
            #pragma unroll
            for (int half = 0; half < 2; half++) {
                int row = rg + am * 16 + half * 8;
                float x0 = acc[am][bn][half * 2]     + bb0;
                float x1 = acc[am][bn][half * 2 + 1] + bb1;
                if (mode) {
                    x0 = x0 >= 0.f ? x0 : 0.01f * x0;
                    x1 = x1 >= 0.f ? x1 : 0.01f * x1;
                }
                size_t base = (size_t)row * Mout + col;
                if (mode <= 1) {
                    float2 v; v.x = x0; v.y = x1;
                    *(float2*)(Cf + base) = v;
                } else {
                    __nv_bfloat16 h0, l0, h1, l1;
                    split2(x0, h0, l0);
                    split2(x1, h1, l1);
                    __nv_bfloat162 ph, pl;
                    ph.x = h0; ph.y = h1;
                    pl.x = l0; pl.y = l1;
                    *(__nv_bfloat162*)(C2h + base) = ph;
                    *(__nv_bfloat162*)(C2l + base) = pl;
                }
            }
        }
    }
}

// ---------------- BiLSTM recurrence (fp32, packed f32x2 FMA) ----------------
__global__ __launch_bounds__(512) void lstm_kernel() {
    int dir = blockIdx.y;
    int b0  = blockIdx.x * 8;
    const float* xg = dir ? g_xgb : g_xgf;
    const float* W4 = dir ? g_Whh4_b : g_Whh4_f;

    __shared__ float hs[8][Hz];
    __shared__ float cs[8][Hz];
    __shared__ float gb[8][G4];

    int g = threadIdx.x;
    uint32_t hs_base = smem_u32(&hs[0][0]);
    for (int idx = g; idx < 8 * Hz; idx += 512) {
        ((float*)hs)[idx] = 0.f;
        ((float*)cs)[idx] = 0.f;
    }
    __syncthreads();

    const float* wptr0 = W4 + (g << 2);

    for (int t = 0; t < Lz; t++) {
        int pos = dir ? (Lz - 1 - t) : t;
        u64t acc[8];
        #pragma unroll
        for (int r = 0; r < 8; r++)
            acc[r] = pack2(xg[((size_t)(b0 + r) * Lz + pos) * G4 + g], 0.f);

        #pragma unroll 8
        for (int kc = 0; kc < Hz / 4; kc++) {
            u64t w01, w23;
            ldg_w2(wptr0 + kc * (G4 * 4), w01, w23);   // (w_k,w_k+1),(w_k+2,w_k+3)
            #pragma unroll
            for (int r = 0; r < 8; r++) {
                u64t h01, h23;
                lds_h2(hs_base + (uint32_t)(r * Hz + (kc << 2)) * 4u, h01, h23);
                acc[r] = fma2(w01, h01, acc[r]);
                acc[r] = fma2(w23, h23, acc[r]);
            }
        }
        #pragma unroll
        for (int r = 0; r < 8; r++) gb[r][g] = hadd2(acc[r]);
        __syncthreads();

        #pragma unroll
        for (int rep = 0; rep < 2; rep++) {
            int idx = rep * 512 + g;
            int r = idx >> 7, j = idx & 127;
            float xi = gb[r][j];
            float xf = gb[r][j + Hz];
            float xc = gb[r][j + 2 * Hz];
            float xo = gb[r][j + 3 * Hz];
            float ii = 1.f / (1.f + expf(-xi));
            float ff = 1.f / (1.f + expf(-xf));
            float gg = tanhf(xc);
            float oo = 1.f / (1.f + expf(-xo));
            float c  = ff * cs[r][j] + ii * gg;
            float h  = oo * tanhf(c);
            cs[r][j] = c;
            hs[r][j] = h;
            size_t o = ((size_t)(b0 + r) * Lz + pos) * Dz + dir * Hz + j;
            __nv_bfloat16 bh, bl;
            split2(h, bh, bl);
            g_Hh[o] = bh; g_Hl[o] = bl;
        }
        __syncthreads();
    }
}

// ---------------- tag projection (writes TRANSPOSED logits [L][B][T]) ----------------
__global__ __launch_bounds__(256) void logits_kernel(
    const float* __restrict__ H2, const float* __restrict__ Wt, const float* __restrict__ bt)
{
    __shared__ float wts[Tz * Dz];
    __shared__ float bts[Tz];
    for (int i = threadIdx.x; i < Tz * Dz; i += 256) wts[i] = Wt[i];
    if (threadIdx.x < Tz) bts[threadIdx.x] = bt[threadIdx.x];
    __syncthreads();

    int n    = (blockIdx.x * 256 + threadIdx.x) >> 5;
    int lane = threadIdx.x & 31;
    if (n >= NL) return;
    float acc[Tz];
    #pragma unroll
    for (int t = 0; t < Tz; t++) acc[t] = 0.f;
    const float* hrow = H2 + (size_t)n * Dz;
    for (int k = lane; k < Dz; k += 32) {
        float x = hrow[k];
        #pragma unroll
        for (int t = 0; t < Tz; t++) acc[t] = fmaf(x, wts[t * Dz + k], acc[t]);
    }
    #pragma unroll
    for (int t = 0; t < Tz; t++)
        #pragma unroll
        for (int off = 16; off; off >>= 1)
            acc[t] += __shfl_xor_sync(0xffffffffu, acc[t], off);
    if (lane == 0) {
        int b = n / Lz, l = n % Lz;
        size_t o = ((size_t)l * Bz + b) * Tz;
        #pragma unroll
        for (int t = 0; t < Tz; t++) {
            float x = acc[t] + bts[t];
            g_logits[o + t] = (x >= 0.f ? x : 0.01f * x);
        }
    }
}

// ---------------- per-sample Viterbi (smem backpointers, packed 3b x 6) ----------------
#define VIT_SMEM (Lz * 128 * 4)
__global__ __launch_bounds__(128) void viterbi_kernel(const float* __restrict__ trans,
                                                      float* __restrict__ out,
                                                      int score_off, int path_off)
{
    extern __shared__ uint32_t bps[];    // [Lz][128]
    __shared__ float tr[Tz * Tz];
    int tid = threadIdx.x;
    if (tid < Tz * Tz) tr[tid] = trans[tid];
    __syncthreads();
    int b = blockIdx.x * 128 + tid;

    float prev[Tz];
    #pragma unroll
    for (int t = 0; t < Tz; t++) prev[t] = g_logits[(size_t)b * Tz + t];

    for (int l = 1; l < Lz; l++) {
        float ob[Tz];
        const float* lg = g_logits + ((size_t)l * Bz + b) * Tz;
        #pragma unroll
        for (int t = 0; t < Tz; t++) ob[t] = lg[t];
        float cur[Tz];
        uint32_t packed = 0;
        #pragma unroll
        for (int j = 0; j < Tz; j++) {
            float best = prev[0] + tr[j];
            int bi = 0;
            #pragma unroll
            for (int i = 1; i < Tz; i++) {
                float v = prev[i] + tr[i * Tz + j];
                if (v > best) { best = v; bi = i; }
            }
            packed |= (uint32_t)bi << (3 * j);
            cur[j] = ob[j] + best;
        }
        bps[l * 128 + tid] = packed;
        #pragma unroll
        for (int j = 0; j < Tz; j++) prev[j] = cur[j];
    }
    float best = prev[0];
    int last = 0;
    #pragma unroll
    for (int i = 1; i < Tz; i++) if (prev[i] > best) { best = prev[i]; last = i; }

    if (score_off >= 0) out[score_off + b] = best;
    if (path_off >= 0) {
        int tag = last;
        out[path_off + (size_t)b * Lz + (Lz - 1)] = (float)tag;
        for (int l = Lz - 1; l >= 1; l--) {
            tag = (bps[l * 128 + tid] >> (3 * tag)) & 7;
            out[path_off + (size_t)b * Lz + (l - 1)] = (float)tag;
        }
    }
}

// ---------------- launch ----------------
extern "C" void kernel_launch(void* const* d_in, const int* in_sizes, int n_in,
                              void* d_out, int out_size) {
    const int*   sent  = (const int*)d_in[0];
    const float* emb   = (const float*)d_in[2];
    const float* Wih_f = (const float*)d_in[3];
    const float* Whh_f = (const float*)d_in[4];
    const float* bih_f = (const float*)d_in[5];
    const float* bhh_f = (const float*)d_in[6];
    const float* Wih_b = (const float*)d_in[7];
    const float* Whh_b = (const float*)d_in[8];
    const float* bih_b = (const float*)d_in[9];
    const float* bhh_b = (const float*)d_in[10];
    const float* W1    = (const float*)d_in[11];
    const float* b1    = (const float*)d_in[12];
    const float* W2    = (const float*)d_in[13];
    const float* b2    = (const float*)d_in[14];
    const float* Wt    = (const float*)d_in[15];
    const float* bt    = (const float*)d_in[16];
    const float* trans = (const float*)d_in[17];
    float* out = (float*)d_out;

    float *X, *xgf, *xgb;
    __nv_bfloat16 *Xh, *Xl, *Hh, *Hl, *M1h, *M1l;
    __nv_bfloat16 *WFh, *WFl, *WBh, *WBl, *W1h, *W1l, *W2h, *W2l;
    cudaGetSymbolAddress((void**)&X,   g_X);
    cudaGetSymbolAddress((void**)&xgf, g_xgf);
    cudaGetSymbolAddress((void**)&xgb, g_xgb);
    cudaGetSymbolAddress((void**)&Xh, g_Xh);   cudaGetSymbolAddress((void**)&Xl, g_Xl);
    cudaGetSymbolAddress((void**)&Hh, g_Hh);   cudaGetSymbolAddress((void**)&Hl, g_Hl);
    cudaGetSymbolAddress((void**)&M1h, g_M1h); cudaGetSymbolAddress((void**)&M1l, g_M1l);
    cudaGetSymbolAddress((void**)&WFh, g_WFh); cudaGetSymbolAddress((void**)&WFl, g_WFl);
    cudaGetSymbolAddress((void**)&WBh, g_WBh); cudaGetSymbolAddress((void**)&WBl, g_WBl);
    cudaGetSymbolAddress((void**)&W1h, g_W1h); cudaGetSymbolAddress((void**)&W1l, g_W1l);
    cudaGetSymbolAddress((void**)&W2h, g_W2h); cudaGetSymbolAddress((void**)&W2l, g_W2l);

    cudaFuncSetAttribute(gemm_mma, cudaFuncAttributeMaxDynamicSharedMemorySize, GEMM_SMEM);
    cudaFuncSetAttribute(viterbi_kernel, cudaFuncAttributeMaxDynamicSharedMemorySize, VIT_SMEM);

    cudaMemsetAsync(d_out, 0, (size_t)out_size * sizeof(float));

    // 1. gather + convert embeddings
    gather_conv<<<NL * (Ez / 4) / 256, 256>>>(sent, emb);
    // 2. convert weights, repack Whh
    conv2<<<(G4 * Ez + 255) / 256, 256>>>(Wih_f, WFh, WFl, G4 * Ez);
    conv2<<<(G4 * Ez + 255) / 256, 256>>>(Wih_b, WBh, WBl, G4 * Ez);
    conv2<<<(Dz * Dz + 255) / 256, 256>>>(W1, W1h, W1l, Dz * Dz);
    conv2<<<(Dz * Dz + 255) / 256, 256>>>(W2, W2h, W2l, Dz * Dz);
    prep_whh<<<(G4 * Hz + 255) / 256, 256>>>(Whh_f, Whh_b);
    // 3. input-gate GEMMs (HMMA split-bf16, pipelined)
    gemm_mma<<<dim3(G4 / 128, NL / 128), 256, GEMM_SMEM>>>(
        Xh, Xl, WFh, WFl, bih_f, bhh_f, xgf, nullptr, nullptr, G4, 0);
    gemm_mma<<<dim3(G4 / 128, NL / 128), 256, GEMM_SMEM>>>(
        Xh, Xl, WBh, WBl, bih_b, bhh_b, xgb, nullptr, nullptr, G4, 0);
    // 4. BiLSTM recurrence (f32x2 packed FMA, writes bf16 split2 hidden)
    lstm_kernel<<<dim3(Bz / 8, 2), 512>>>();
    // 5. MLP1 (split2 out) and MLP2 (fp32 out)
    gemm_mma<<<dim3(Dz / 128, NL / 128), 256, GEMM_SMEM>>>(
        Hh, Hl, W1h, W1l, b1, nullptr, nullptr, M1h, M1l, Dz, 2);
    gemm_mma<<<dim3(Dz / 128, NL / 128), 256, GEMM_SMEM>>>(
        M1h, M1l, W2h, W2l, b2, nullptr, X, nullptr, nullptr, Dz, 1);
    // 6. tag projection (transposed logits)
    logits_kernel<<<NL / 8, 256>>>(X, Wt, bt);
    // 7. viterbi + output
    int score_off = -1, path_off = -1;
    if (out_size >= Bz * (Lz + 1))      { score_off = 0; path_off = Bz; }
    else if (out_size >= Bz * Lz)       { path_off = 0; }
    else                                { score_off = 0; }
    viterbi_kernel<<<Bz / 128, 128, VIT_SMEM>>>(trans, out, score_off, path_off);
}

// round 12
// speedup vs baseline: 1.8751x; 1.0448x over previous
#include <cuda_runtime.h>
#include <cuda_bf16.h>
#include <cstdint>
#include <math.h>

#define Bz 512
#define Lz 200
#define Ez 256
#define Hz 128
#define G4 512          // 4*H
#define Dz 256
#define Tz 6
#define NL (Bz*Lz)      // 102400

typedef unsigned long long u64t;

// ---------------- device scratch ----------------
__device__ float g_X[NL*Dz];          // h2 (MLP2 fp32 output)
__device__ float g_xgf[NL*G4];        // forward input gates (fp32)
__device__ float g_xgb[NL*G4];        // backward input gates (fp32)
__device__ float g_logits[NL*Tz];     // emissions, TRANSPOSED layout [L][B][T]
__device__ float g_Whh4_f[Hz*G4];
__device__ float g_Whh4_b[Hz*G4];

// bf16 split-2 operand buffers (value = hi + lo)
__device__ __nv_bfloat16 g_Xh[NL*Ez],  g_Xl[NL*Ez];     // embeddings
__device__ __nv_bfloat16 g_Hh[NL*Dz],  g_Hl[NL*Dz];     // BiLSTM hidden
__device__ __nv_bfloat16 g_M1h[NL*Dz], g_M1l[NL*Dz];    // MLP1 out
__device__ __nv_bfloat16 g_WFh[G4*Ez], g_WFl[G4*Ez];    // Wih_f
__device__ __nv_bfloat16 g_WBh[G4*Ez], g_WBl[G4*Ez];    // Wih_b
__device__ __nv_bfloat16 g_W1h[Dz*Dz], g_W1l[Dz*Dz];
__device__ __nv_bfloat16 g_W2h[Dz*Dz], g_W2l[Dz*Dz];

// ================= helpers =================
__device__ __forceinline__ uint32_t smem_u32(const void* p) {
    uint32_t a;
    asm("{ .reg .u64 t; cvta.to.shared.u64 t, %1; cvt.u32.u64 %0, t; }" : "=r"(a) : "l"(p));
    return a;
}
__device__ __forceinline__ uint32_t swz(uint32_t off) {        // SW128-style XOR swizzle
    return off ^ ((off >> 3) & 0x70);
}
__device__ __forceinline__ void ldm4(uint32_t* r, uint32_t addr) {
    asm volatile("ldmatrix.sync.aligned.m8n8.x4.shared.b16 {%0,%1,%2,%3}, [%4];"
        : "=r"(r[0]), "=r"(r[1]), "=r"(r[2]), "=r"(r[3]) : "r"(addr));
}
__device__ __forceinline__ void mma16816(float* d, const uint32_t* a, const uint32_t* b) {
    asm volatile("mma.sync.aligned.m16n8k16.row.col.f32.bf16.bf16.f32 "
        "{%0,%1,%2,%3}, {%4,%5,%6,%7}, {%8,%9}, {%0,%1,%2,%3};"
        : "+f"(d[0]), "+f"(d[1]), "+f"(d[2]), "+f"(d[3])
        : "r"(a[0]), "r"(a[1]), "r"(a[2]), "r"(a[3]), "r"(b[0]), "r"(b[1]));
}
__device__ __forceinline__ void split2(float x, __nv_bfloat16& h, __nv_bfloat16& l) {
    h = __float2bfloat16(x);
    l = __float2bfloat16(x - __bfloat162float(h));
}
__device__ __forceinline__ void cp16(uint32_t dst, const void* src) {
    asm volatile("cp.async.cg.shared.global [%0], [%1], 16;" :: "r"(dst), "l"(src));
}
// packed f32x2 FMA (Blackwell)
__device__ __forceinline__ u64t fma2(u64t a, u64t b, u64t c) {
    u64t d;
    asm("fma.rn.f32x2 %0, %1, %2, %3;" : "=l"(d) : "l"(a), "l"(b), "l"(c));
    return d;
}
__device__ __forceinline__ u64t pack2(float x, float y) {
    u64t r; asm("mov.b64 %0, {%1, %2};" : "=l"(r) : "f"(x), "f"(y)); return r;
}
__device__ __forceinline__ float hadd2(u64t v) {
    float x, y;
    asm("mov.b64 {%0, %1}, %2;" : "=f"(x), "=f"(y) : "l"(v));
    return x + y;
}
__device__ __forceinline__ void ldg_w2(const float* p, u64t& a, u64t& b) {
    asm("ld.global.nc.L1::evict_last.v2.u64 {%0,%1}, [%2];" : "=l"(a), "=l"(b) : "l"(p));
}
// ORDERING-SAFE shared load: volatile + memory clobber. Without this the
// compiler can hoist ld.shared across __syncthreads()/hs-stores (R10/R11 bug).
__device__ __forceinline__ void lds_h2v(uint32_t addr, u64t& a, u64t& b) {
    asm volatile("ld.shared.v2.u64 {%0,%1}, [%2];" : "=l"(a), "=l"(b) : "r"(addr) : "memory");
}

// ---------------- gather embeddings -> bf16 split2 ----------------
__global__ void gather_conv(const int* __restrict__ sent, const float* __restrict__ emb) {
    int idx = blockIdx.x * 256 + threadIdx.x;     // float4 units over NL x 256
    if (idx >= NL * (Ez / 4)) return;
    int n = idx >> 6, e4 = idx & 63;
    int tok = sent[n];
    float4 v = ((const float4*)emb)[(size_t)tok * 64 + e4];
    size_t o = (size_t)idx * 4;
    float vv[4] = {v.x, v.y, v.z, v.w};
    __nv_bfloat16 hh[4], ll[4];
    #pragma unroll
    for (int k = 0; k < 4; k++) split2(vv[k], hh[k], ll[k]);
    __nv_bfloat162 p;
    p.x = hh[0]; p.y = hh[1]; ((__nv_bfloat162*)(g_Xh + o))[0] = p;
    p.x = hh[2]; p.y = hh[3]; ((__nv_bfloat162*)(g_Xh + o))[1] = p;
    p.x = ll[0]; p.y = ll[1]; ((__nv_bfloat162*)(g_Xl + o))[0] = p;
    p.x = ll[2]; p.y = ll[3]; ((__nv_bfloat162*)(g_Xl + o))[1] = p;
}

// ---------------- fp32 -> split2 ----------------
__global__ void conv2(const float* __restrict__ src, __nv_bfloat16* __restrict__ hi,
                      __nv_bfloat16* __restrict__ lo, int n) {
    int i = blockIdx.x * 256 + threadIdx.x;
    if (i >= n) return;
    __nv_bfloat16 h, l;
    split2(src[i], h, l);
    hi[i] = h; lo[i] = l;
}

// ---------------- repack Whh ----------------
__global__ void prep_whh(const float* __restrict__ Whh_f, const float* __restrict__ Whh_b) {
    int idx = blockIdx.x * 256 + threadIdx.x;
    if (idx >= G4 * Hz) return;
    int g = idx / Hz, k = idx % Hz;
    int dst = (k >> 2) * (G4 * 4) + g * 4 + (k & 3);
    g_Whh4_f[dst] = Whh_f[idx];
    g_Whh4_b[dst] = Whh_b[idx];
}

// ================= HMMA split-bf16 GEMM (cp.async double-buffered) =================
#define GEMM_SMEM 65536
__global__ __launch_bounds__(256) void gemm_mma(
    const __nv_bfloat16* __restrict__ Ah, const __nv_bfloat16* __restrict__ Al,
    const __nv_bfloat16* __restrict__ Bh, const __nv_bfloat16* __restrict__ Bl,
    const float* __restrict__ bias1, const float* __restrict__ bias2,
    float* __restrict__ Cf,
    __nv_bfloat16* __restrict__ C2h, __nv_bfloat16* __restrict__ C2l,
    int Mout, int mode)
{
    extern __shared__ __align__(1024) char dynsm[];
    uint32_t smem_base = smem_u32(dynsm);

    int tid = threadIdx.x, wid = tid >> 5, lane = tid & 31;
    int row0 = blockIdx.y * 128;
    int col0 = blockIdx.x * 128;
    int wm0 = (wid & 1) * 64;
    int wn0 = (wid >> 1) * 32;

    float acc[4][4][4];
    #pragma unroll
    for (int i = 0; i < 4; i++)
        #pragma unroll
        for (int j = 0; j < 4; j++)
            #pragma unroll
            for (int k = 0; k < 4; k++) acc[i][j][k] = 0.f;

    int arow = ((lane >> 3) & 1) * 8 + (lane & 7);
    int acb  = (lane >> 4) << 4;
    int brow = ((lane >> 4) << 3) + (lane & 7);
    int bcb  = ((lane >> 3) & 1) << 4;

#define LOAD_CHUNK(kcv, bufi) do {                                                      \
        int k0_ = (kcv) * 32;                                                           \
        uint32_t sb_ = smem_base + (bufi) * 32768;                                      \
        _Pragma("unroll")                                                               \
        for (int j_ = 0; j_ < 4; j_++) {                                                \
            int idx_ = tid + j_ * 256;                                                  \
            int r_ = idx_ >> 3, s_ = idx_ & 7;                                          \
            const __nv_bfloat16* pa_ = (s_ < 4 ? Ah : Al) + (size_t)(row0 + r_) * 256 + k0_ + (s_ & 3) * 8; \
            cp16(sb_ + swz(r_ * 128 + s_ * 16), pa_);                                   \
            const __nv_bfloat16* pb_ = (s_ < 4 ? Bh : Bl) + (size_t)(col0 + r_) * 256 + k0_ + (s_ & 3) * 8; \
            cp16(sb_ + 16384 + swz(r_ * 128 + s_ * 16), pb_);                           \
        }                                                                               \
        asm volatile("cp.async.commit_group;" ::: "memory");                            \
    } while (0)

    LOAD_CHUNK(0, 0);

    for (int kc = 0; kc < 8; kc++) {
        if (kc < 7) {
            LOAD_CHUNK(kc + 1, (kc + 1) & 1);
            asm volatile("cp.async.wait_group 1;" ::: "memory");
        } else {
            asm volatile("cp.async.wait_group 0;" ::: "memory");
        }
        __syncthreads();

        uint32_t sA = smem_base + (kc & 1) * 32768;
        uint32_t sB = sA + 16384;

        #pragma unroll
        for (int ks = 0; ks < 2; ks++) {
            uint32_t aH[4][4], aL[4][4], bH[2][4], bL[2][4];
            #pragma unroll
            for (int am = 0; am < 4; am++) {
                int r = wm0 + am * 16 + arow;
                ldm4(aH[am], sA + swz((uint32_t)(r * 128 + ks * 32 + acb)));
                ldm4(aL[am], sA + swz((uint32_t)(r * 128 + 64 + ks * 32 + acb)));
            }
            #pragma unroll
            for (int np = 0; np < 2; np++) {
                int r = wn0 + np * 16 + brow;
                ldm4(bH[np], sB + swz((uint32_t)(r * 128 + ks * 32 + bcb)));
                ldm4(bL[np], sB + swz((uint32_t)(r * 128 + 64 + ks * 32 + bcb)));
            }
            #pragma unroll
            for (int am = 0; am < 4; am++) {
                #pragma unroll
                for (int bn = 0; bn < 4; bn++) {
                    const uint32_t* bh = &bH[bn >> 1][(bn & 1) * 2];
                    const uint32_t* bl = &bL[bn >> 1][(bn & 1) * 2];
                    mma16816(acc[am][bn], aH[am], bh);
                    mma16816(acc[am][bn], aH[am], bl);
                    mma16816(acc[am][bn], aL[am], bh);
                }
            }
        }
        __syncthreads();
    }
#undef LOAD_CHUNK

    int rg = row0 + wm0 + (lane >> 2);
    int cg = col0 + wn0 + (lane & 3) * 2;
    #pragma unroll
    for (int bn = 0; bn < 4; bn++) {
        int col = cg + bn * 8;
        float bb0 = bias1[col]     + (bias2 ? bias2[col]     : 0.f);
        float bb1 = bias1[col + 1] + (bias2 ? bias2[col + 1] : 0.f);
        #pragma unroll
        for (int am = 0; am < 4; am++) {
            #pragma unroll
            for (int half = 0; half < 2; half++) {
                int row = rg + am * 16 + half * 8;
                float x0 = acc[am][bn][half * 2]     + bb0;
                float x1 = acc[am][bn][half * 2 + 1] + bb1;
                if (mode) {
                    x0 = x0 >= 0.f ? x0 : 0.01f * x0;
                    x1 = x1 >= 0.f ? x1 : 0.01f * x1;
                }
                size_t base = (size_t)row * Mout + col;
                if (mode <= 1) {
                    float2 v; v.x = x0; v.y = x1;
                    *(float2*)(Cf + base) = v;
                } else {
                    __nv_bfloat16 h0, l0, h1, l1;
                    split2(x0, h0, l0);
                    split2(x1, h1, l1);
                    __nv_bfloat162 ph, pl;
                    ph.x = h0; ph.y = h1;
                    pl.x = l0; pl.y = l1;
                    *(__nv_bfloat162*)(C2h + base) = ph;
                    *(__nv_bfloat162*)(C2l + base) = pl;
                }
            }
        }
    }
}

// ---------------- BiLSTM recurrence ----------------
// 20/32 kc-chunks (160KB) of Whh staged in dynamic SMEM once; remaining 12
// chunks (96KB) prefetched per-step into registers. All shared loads use the
// volatile+memory-clobber form (lds_h2v) so they cannot be hoisted across
// __syncthreads()/hs stores. EXACT activations.
#define KC_SM 20
#define KC_LD (Hz/4 - KC_SM)     // 12
#define LSTM_DYN (KC_SM * 2048 * 4)
__global__ __launch_bounds__(512) void lstm_kernel() {
    extern __shared__ __align__(16) float sw[];    // [KC_SM][2048]
    __shared__ float hs[8][Hz];
    __shared__ float cs[8][Hz];
    __shared__ float gb[8][G4];

    int dir = blockIdx.y;
    int b0  = blockIdx.x * 8;
    const float* xg = dir ? g_xgb : g_xgf;
    const float* W4 = dir ? g_Whh4_b : g_Whh4_f;

    int g = threadIdx.x;
    // cooperative smem weight load
    for (int i = g * 4; i < KC_SM * 2048; i += 512 * 4)
        *(float4*)(sw + i) = *(const float4*)(W4 + i);
    for (int idx = g; idx < 8 * Hz; idx += 512) {
        ((float*)hs)[idx] = 0.f;
        ((float*)cs)[idx] = 0.f;
    }
    __syncthreads();

    uint32_t hs_base = smem_u32(&hs[0][0]);
    uint32_t sw_g    = smem_u32(sw) + (uint32_t)(g << 4);      // + kc*8192 bytes
    const float* wg0 = W4 + KC_SM * 2048 + (g << 2);

    for (int t = 0; t < Lz; t++) {
        int pos = dir ? (Lz - 1 - t) : t;

        // prefetch the 12 L2-resident weight chunks for this thread
        u64t wp0[KC_LD], wp1[KC_LD];
        #pragma unroll
        for (int kc = 0; kc < KC_LD; kc++)
            ldg_w2(wg0 + kc * 2048, wp0[kc], wp1[kc]);

        u64t acc[8];
        #pragma unroll
        for (int r = 0; r < 8; r++)
            acc[r] = pack2(xg[((size_t)(b0 + r) * Lz + pos) * G4 + g], 0.f);

        // smem-weight portion
        #pragma unroll 4
        for (int kc = 0; kc < KC_SM; kc++) {
            u64t w01, w23;
            lds_h2v(sw_g + (uint32_t)kc * 8192u, w01, w23);
            #pragma unroll
            for (int r = 0; r < 8; r++) {
                u64t h01, h23;
                lds_h2v(hs_base + (uint32_t)(r * Hz + (kc << 2)) * 4u, h01, h23);
                acc[r] = fma2(w01, h01, acc[r]);
                acc[r] = fma2(w23, h23, acc[r]);
            }
        }
        // register-prefetched portion
        #pragma unroll
        for (int kc = 0; kc < KC_LD; kc++) {
            #pragma unroll
            for (int r = 0; r < 8; r++) {
                u64t h01, h23;
                lds_h2v(hs_base + (uint32_t)(r * Hz + ((KC_SM + kc) << 2)) * 4u, h01, h23);
                acc[r] = fma2(wp0[kc], h01, acc[r]);
                acc[r] = fma2(wp1[kc], h23, acc[r]);
            }
        }
        #pragma unroll
        for (int r = 0; r < 8; r++) gb[r][g] = hadd2(acc[r]);
        __syncthreads();

        #pragma unroll
        for (int rep = 0; rep < 2; rep++) {
            int idx = rep * 512 + g;
            int r = idx >> 7, j = idx & 127;
            float xi = gb[r][j];
            float xf = gb[r][j + Hz];
            float xc = gb[r][j + 2 * Hz];
            float xo = gb[r][j + 3 * Hz];
            float ii = 1.f / (1.f + expf(-xi));
            float ff = 1.f / (1.f + expf(-xf));
            float gg = tanhf(xc);
            float oo = 1.f / (1.f + expf(-xo));
            float c  = ff * cs[r][j] + ii * gg;
            float h  = oo * tanhf(c);
            cs[r][j] = c;
            hs[r][j] = h;
            size_t o = ((size_t)(b0 + r) * Lz + pos) * Dz + dir * Hz + j;
            __nv_bfloat16 bh, bl;
            split2(h, bh, bl);
            g_Hh[o] = bh; g_Hl[o] = bl;
        }
        __syncthreads();
    }
}

// ---------------- tag projection (writes TRANSPOSED logits [L][B][T]) ----------------
__global__ __launch_bounds__(256) void logits_kernel(
    const float* __restrict__ H2, const float* __restrict__ Wt, const float* __restrict__ bt)
{
    __shared__ float wts[Tz * Dz];
    __shared__ float bts[Tz];
    for (int i = threadIdx.x; i < Tz * Dz; i += 256) wts[i] = Wt[i];
    if (threadIdx.x < Tz) bts[threadIdx.x] = bt[threadIdx.x];
    __syncthreads();

    int n    = (blockIdx.x * 256 + threadIdx.x) >> 5;
    int lane = threadIdx.x & 31;
    if (n >= NL) return;
    float acc[Tz];
    #pragma unroll
    for (int t = 0; t < Tz; t++) acc[t] = 0.f;
    const float* hrow = H2 + (size_t)n * Dz;
    for (int k = lane; k < Dz; k += 32) {
        float x = hrow[k];
        #pragma unroll
        for (int t = 0; t < Tz; t++) acc[t] = fmaf(x, wts[t * Dz + k], acc[t]);
    }
    #pragma unroll
    for (int t = 0; t < Tz; t++)
        #pragma unroll
        for (int off = 16; off; off >>= 1)
            acc[t] += __shfl_xor_sync(0xffffffffu, acc[t], off);
    if (lane == 0) {
        int b = n / Lz, l = n % Lz;
        size_t o = ((size_t)l * Bz + b) * Tz;
        #pragma unroll
        for (int t = 0; t < Tz; t++) {
            float x = acc[t] + bts[t];
            g_logits[o + t] = (x >= 0.f ? x : 0.01f * x);
        }
    }
}

// ---------------- per-sample Viterbi (smem backpointers, packed 3b x 6) ----------------
#define VIT_SMEM (Lz * 128 * 4)
__global__ __launch_bounds__(128) void viterbi_kernel(const float* __restrict__ trans,
                                                      float* __restrict__ out,
                                                      int score_off, int path_off)
{
    extern __shared__ uint32_t bps[];    // [Lz][128]
    __shared__ float tr[Tz * Tz];
    int tid = threadIdx.x;
    if (tid < Tz * Tz) tr[tid] = trans[tid];
    __syncthreads();
    int b = blockIdx.x * 128 + tid;

    float prev[Tz];
    #pragma unroll
    for (int t = 0; t < Tz; t++) prev[t] = g_logits[(size_t)b * Tz + t];

    for (int l = 1; l < Lz; l++) {
        float ob[Tz];
        const float* lg = g_logits + ((size_t)l * Bz + b) * Tz;
        #pragma unroll
        for (int t = 0; t < Tz; t++) ob[t] = lg[t];
        float cur[Tz];
        uint32_t packed = 0;
        #pragma unroll
        for (int j = 0; j < Tz; j++) {
            float best = prev[0] + tr[j];
            int bi = 0;
            #pragma unroll
            for (int i = 1; i < Tz; i++) {
                float v = prev[i] + tr[i * Tz + j];
                if (v > best) { best = v; bi = i; }
            }
            packed |= (uint32_t)bi << (3 * j);
            cur[j] = ob[j] + best;
        }
        bps[l * 128 + tid] = packed;
        #pragma unroll
        for (int j = 0; j < Tz; j++) prev[j] = cur[j];
    }
    float best = prev[0];
    int last = 0;
    #pragma unroll
    for (int i = 1; i < Tz; i++) if (prev[i] > best) { best = prev[i]; last = i; }

    if (score_off >= 0) out[score_off + b] = best;
    if (path_off >= 0) {
        int tag = last;
        out[path_off + (size_t)b * Lz + (Lz - 1)] = (float)tag;
        for (int l = Lz - 1; l >= 1; l--) {
            tag = (bps[l * 128 + tid] >> (3 * tag)) & 7;
            out[path_off + (size_t)b * Lz + (l - 1)] = (float)tag;
        }
    }
}

// ---------------- launch ----------------
extern "C" void kernel_launch(void* const* d_in, const int* in_sizes, int n_in,
                              void* d_out, int out_size) {
    const int*   sent  = (const int*)d_in[0];
    const float* emb   = (const float*)d_in[2];
    const float* Wih_f = (const float*)d_in[3];
    const float* Whh_f = (const float*)d_in[4];
    const float* bih_f = (const float*)d_in[5];
    const float* bhh_f = (const float*)d_in[6];
    const float* Wih_b = (const float*)d_in[7];
    const float* Whh_b = (const float*)d_in[8];
    const float* bih_b = (const float*)d_in[9];
    const float* bhh_b = (const float*)d_in[10];
    const float* W1    = (const float*)d_in[11];
    const float* b1    = (const float*)d_in[12];
    const float* W2    = (const float*)d_in[13];
    const float* b2    = (const float*)d_in[14];
    const float* Wt    = (const float*)d_in[15];
    const float* bt    = (const float*)d_in[16];
    const float* trans = (const float*)d_in[17];
    float* out = (float*)d_out;

    float *X, *xgf, *xgb;
    __nv_bfloat16 *Xh, *Xl, *Hh, *Hl, *M1h, *M1l;
    __nv_bfloat16 *WFh, *WFl, *WBh, *WBl, *W1h, *W1l, *W2h, *W2l;
    cudaGetSymbolAddress((void**)&X,   g_X);
    cudaGetSymbolAddress((void**)&xgf, g_xgf);
    cudaGetSymbolAddress((void**)&xgb, g_xgb);
    cudaGetSymbolAddress((void**)&Xh, g_Xh);   cudaGetSymbolAddress((void**)&Xl, g_Xl);
    cudaGetSymbolAddress((void**)&Hh, g_Hh);   cudaGetSymbolAddress((void**)&Hl, g_Hl);
    cudaGetSymbolAddress((void**)&M1h, g_M1h); cudaGetSymbolAddress((void**)&M1l, g_M1l);
    cudaGetSymbolAddress((void**)&WFh, g_WFh); cudaGetSymbolAddress((void**)&WFl, g_WFl);
    cudaGetSymbolAddress((void**)&WBh, g_WBh); cudaGetSymbolAddress((void**)&WBl, g_WBl);
    cudaGetSymbolAddress((void**)&W1h, g_W1h); cudaGetSymbolAddress((void**)&W1l, g_W1l);
    cudaGetSymbolAddress((void**)&W2h, g_W2h); cudaGetSymbolAddress((void**)&W2l, g_W2l);

    cudaFuncSetAttribute(gemm_mma, cudaFuncAttributeMaxDynamicSharedMemorySize, GEMM_SMEM);
    cudaFuncSetAttribute(viterbi_kernel, cudaFuncAttributeMaxDynamicSharedMemorySize, VIT_SMEM);
    cudaFuncSetAttribute(lstm_kernel, cudaFuncAttributeMaxDynamicSharedMemorySize, LSTM_DYN);

    cudaMemsetAsync(d_out, 0, (size_t)out_size * sizeof(float));

    // 1. gather + convert embeddings
    gather_conv<<<NL * (Ez / 4) / 256, 256>>>(sent, emb);
    // 2. convert weights, repack Whh
    conv2<<<(G4 * Ez + 255) / 256, 256>>>(Wih_f, WFh, WFl, G4 * Ez);
    conv2<<<(G4 * Ez + 255) / 256, 256>>>(Wih_b, WBh, WBl, G4 * Ez);
    conv2<<<(Dz * Dz + 255) / 256, 256>>>(W1, W1h, W1l, Dz * Dz);
    conv2<<<(Dz * Dz + 255) / 256, 256>>>(W2, W2h, W2l, Dz * Dz);
    prep_whh<<<(G4 * Hz + 255) / 256, 256>>>(Whh_f, Whh_b);
    // 3. input-gate GEMMs (HMMA split-bf16, pipelined)
    gemm_mma<<<dim3(G4 / 128, NL / 128), 256, GEMM_SMEM>>>(
        Xh, Xl, WFh, WFl, bih_f, bhh_f, xgf, nullptr, nullptr, G4, 0);
    gemm_mma<<<dim3(G4 / 128, NL / 128), 256, GEMM_SMEM>>>(
        Xh, Xl, WBh, WBl, bih_b, bhh_b, xgb, nullptr, nullptr, G4, 0);
    // 4. BiLSTM recurrence (smem-staged weights, ordering-safe loads, exact activations)
    lstm_kernel<<<dim3(Bz / 8, 2), 512, LSTM_DYN>>>();
    // 5. MLP1 (split2 out) and MLP2 (fp32 out)
    gemm_mma<<<dim3(Dz / 128, NL / 128), 256, GEMM_SMEM>>>(
        Hh, Hl, W1h, W1l, b1, nullptr, nullptr, M1h, M1l, Dz, 2);
    gemm_mma<<<dim3(Dz / 128, NL / 128), 256, GEMM_SMEM>>>(
        M1h, M1l, W2h, W2l, b2, nullptr, X, nullptr, nullptr, Dz, 1);
    // 6. tag projection (transposed logits)
    logits_kernel<<<NL / 8, 256>>>(X, Wt, bt);
    // 7. viterbi + output
    int score_off = -1, path_off = -1;
    if (out_size >= Bz * (Lz + 1))      { score_off = 0; path_off = Bz; }
    else if (out_size >= Bz * Lz)       { path_off = 0; }
    else                                { score_off = 0; }
    viterbi_kernel<<<Bz / 128, 128, VIT_SMEM>>>(trans, out, score_off, path_off);
}